// round 7
// baseline (speedup 1.0000x reference)
#include <cuda_runtime.h>
#include <cuda_bf16.h>
#include <cstddef>

// ---------------------------------------------------------------------------
// SNN forward: ONE persistent kernel over all T=100 steps with software grid
// barriers. All inter-block data goes through L2 only (stcg/ldcg/cp.async.cg)
// because L1 is neither coherent nor flushed inside a single kernel.
// ---------------------------------------------------------------------------

#define B     128
#define T     100
#define DIN   700
#define DINP  704
#define H     1024
#define O     20
#define KT    16        // k-tile
#define NT    64        // neurons per block tile
#define NBLK  296       // persistent grid (148 SMs x 2, guaranteed resident)
#define SCALE 0.09999950000374997f   // 0.1 / sqrt(1 + 1e-5)

typedef unsigned long long ull;

// ---- device scratch ----
__device__ float g_XT[T * DINP * B];            // [t][i][b], rows 700..703 zero
__device__ float g_W1cat[H * (DINP + H)];       // [n][1728] = [w1x pad704 | w1r]
__device__ float g_W2cat[H * (2 * H)];          // [n][2048] = [w2x | w2r]
__device__ float g_state[12 * H * B];           // [parity][6][H*B]
__device__ float g_m3[2 * O * B];
__device__ float g_d1[H * B];
__device__ float g_d2[H * B];
__device__ float g_d3[O * B];
__device__ float g_part[18 * H * B];            // dense split-K partials
__device__ float g_partMA[16 * H * B];          // tau partials [m/a][8][H*B]
__device__ unsigned g_arrive;
__device__ unsigned g_phase;

enum { MEM1 = 0, SPK1, BB1, MEM2, SPK2, BB2 };

// ---- packed f32x2 helpers ----
__device__ __forceinline__ void fma2(ull& d, ull a, ull b) {
    asm("fma.rn.f32x2 %0, %1, %2, %0;" : "+l"(d) : "l"(a), "l"(b));
}
__device__ __forceinline__ ull dup2(float w) {
    ull r; asm("mov.b64 %0, {%1, %1};" : "=l"(r) : "f"(w)); return r;
}
__device__ __forceinline__ float2 unp2(ull v) {
    float2 r; asm("mov.b64 {%0, %1}, %2;" : "=f"(r.x), "=f"(r.y) : "l"(v)); return r;
}
__device__ __forceinline__ float sigmf(float x) { return 1.0f / (1.0f + expf(-x)); }

// ---- cp.async helpers (cg: L2-only, bypasses L1) ----
__device__ __forceinline__ void cpa16(float* dst_smem, const float* src) {
    unsigned d = (unsigned)__cvta_generic_to_shared(dst_smem);
    asm volatile("cp.async.cg.shared.global [%0], [%1], 16;\n" :: "r"(d), "l"(src));
}
__device__ __forceinline__ void cpa_commit() {
    asm volatile("cp.async.commit_group;\n" ::: "memory");
}
template<int N> __device__ __forceinline__ void cpa_wait() {
    asm volatile("cp.async.wait_group %0;\n" :: "n"(N) : "memory");
}

// ---- grid-wide barrier (sense via generation counter) ----
__device__ __forceinline__ void grid_bar(unsigned& gen) {
    __syncthreads();
    if (threadIdx.x == 0) {
        __threadfence();
        unsigned t = atomicAdd(&g_arrive, 1u);
        if (t == NBLK - 1) {
            *(volatile unsigned*)&g_arrive = 0u;
            __threadfence();
            atomicAdd(&g_phase, 1u);
        } else {
            volatile unsigned* ph = &g_phase;
            while (*ph == gen) { __nanosleep(64); }
            __threadfence();
        }
    }
    __syncthreads();
    gen++;
}

// ---------------------------------------------------------------------------
// Tiled GEMM job: partial[n0..n0+64][0..128] += A[k][b]*W[n][k] over k-tiles
// [tb,te). A from 2 concatenated segments, boundary at tiles_seg1*KT.
// 8 warps; warp owns 8 neurons; lane owns 4 batch rows. Smem 24KB dbl-buffered.
// ---------------------------------------------------------------------------
__device__ __forceinline__ void gemm_job(
    const float* __restrict__ Aseg1, const float* __restrict__ Aseg2,
    int tiles_seg1,
    const float* __restrict__ W, int Ktot,
    int tb, int te, int n0,
    float* __restrict__ partial,
    float* __restrict__ Abuf,      // [2][KT*B]
    float* __restrict__ Wbuf)      // [2][NT*KT]
{
    const int tid  = threadIdx.x;
    const int warp = tid >> 5, lane = tid & 31;
    const int seg1K = tiles_seg1 * KT;

    auto load_tile = [&](int tt, int buf) {
        const int kbase = tt * KT;
        const float* Ap = (tt < tiles_seg1) ? (Aseg1 + (size_t)kbase * B)
                                            : (Aseg2 + (size_t)(kbase - seg1K) * B);
        float* Ad = Abuf + buf * (KT * B);
        #pragma unroll
        for (int i = 0; i < 2; i++) {               // 512 float4, 2 per thread
            int f4 = tid + i * 256;
            cpa16(Ad + f4 * 4, Ap + f4 * 4);
        }
        float* Wd = Wbuf + buf * (NT * KT);
        {                                            // 256 float4, 1 per thread
            int f4 = tid;
            int j = f4 >> 2, c = f4 & 3;             // 4 float4 per 16-float row
            cpa16(Wd + j * KT + c * 4, W + (size_t)(n0 + j) * Ktot + kbase + c * 4);
        }
        cpa_commit();
    };

    ull acc[8][2];
    #pragma unroll
    for (int j = 0; j < 8; j++) { acc[j][0] = 0ull; acc[j][1] = 0ull; }

    const int nb = te - tb;
    load_tile(tb, 0);

    for (int t = 0; t < nb; t++) {
        const int buf = t & 1;
        if (t + 1 < nb) { load_tile(tb + t + 1, (t + 1) & 1); cpa_wait<1>(); }
        else            { cpa_wait<0>(); }
        __syncthreads();

        const float* As = Abuf + buf * (KT * B) + lane * 4;
        const float* Ws = Wbuf + buf * (NT * KT) + (warp * 8) * KT;
        #pragma unroll
        for (int kk = 0; kk < KT; kk += 4) {
            ulonglong2 a0 = *(const ulonglong2*)(As + (kk + 0) * B);
            ulonglong2 a1 = *(const ulonglong2*)(As + (kk + 1) * B);
            ulonglong2 a2 = *(const ulonglong2*)(As + (kk + 2) * B);
            ulonglong2 a3 = *(const ulonglong2*)(As + (kk + 3) * B);
            #pragma unroll
            for (int j = 0; j < 8; j++) {
                float4 w = *(const float4*)(Ws + j * KT + kk);
                ull w0 = dup2(w.x), w1 = dup2(w.y), w2 = dup2(w.z), w3 = dup2(w.w);
                fma2(acc[j][0], a0.x, w0); fma2(acc[j][1], a0.y, w0);
                fma2(acc[j][0], a1.x, w1); fma2(acc[j][1], a1.y, w1);
                fma2(acc[j][0], a2.x, w2); fma2(acc[j][1], a2.y, w2);
                fma2(acc[j][0], a3.x, w3); fma2(acc[j][1], a3.y, w3);
            }
        }
        __syncthreads();
    }

    float* outp = partial + (size_t)(n0 + warp * 8) * B + lane * 4;
    #pragma unroll
    for (int j = 0; j < 8; j++) {
        float2 lo = unp2(acc[j][0]), hi = unp2(acc[j][1]);
        __stcg((float4*)(outp + j * B), make_float4(lo.x, lo.y, hi.x, hi.y));
    }
}

// ---------------------------------------------------------------------------
// The persistent kernel: all 100 timesteps.
// ---------------------------------------------------------------------------
__global__ __launch_bounds__(256, 2) void snn_persist_k(
    const float* __restrict__ XT,
    const float* __restrict__ W1C, const float* __restrict__ W2C,
    const float* __restrict__ b1x, const float* __restrict__ b1r,
    const float* __restrict__ w1m, const float* __restrict__ b1m,
    const float* __restrict__ w1a, const float* __restrict__ b1a,
    const float* __restrict__ b2x, const float* __restrict__ b2r,
    const float* __restrict__ w2m, const float* __restrict__ b2m,
    const float* __restrict__ w2a, const float* __restrict__ b2a,
    const float* __restrict__ w3x, const float* __restrict__ b3x,
    const float* __restrict__ w3m, const float* __restrict__ b3m,
    float* __restrict__ ST, float* __restrict__ M3,
    float* __restrict__ D1, float* __restrict__ D2, float* __restrict__ D3,
    float* __restrict__ PART, float* __restrict__ PARTMA,
    float* __restrict__ out)
{
    __shared__ float smem[2 * KT * B + 2 * NT * KT];   // 24 KB
    float* Abuf = smem;
    float* Wbuf = smem + 2 * KT * B;

    const int bid = blockIdx.x;
    const int tid = threadIdx.x;
    const size_t HB = (size_t)H * B;
    unsigned gen = 0;

    #define STQ(p, s) (ST + ((size_t)(p) * 6 + (s)) * HB)

    for (int t = 0; t < T; t++) {
        const int p = t & 1, q = p ^ 1;

        // ---- P1: dense1 partials (K=1728 = 108 tiles, 18 splits x 16 ntiles) ----
        if (bid < 288) {
            const int nt = bid & 15, s = bid >> 4;
            gemm_job(XT + (size_t)t * DINP * B, STQ(p, SPK1), 44, W1C, DINP + H,
                     s * 6, s * 6 + 6, nt * NT, PART + (size_t)s * HB, Abuf, Wbuf);
        }
        grid_bar(gen);

        // ---- P2: reduce D1 ----
        {
            const int idx = bid * 256 + tid;
            if (idx < (int)(HB / 4)) {
                const size_t off = (size_t)idx * 4;
                float4 s4 = make_float4(0.f, 0.f, 0.f, 0.f);
                for (int k = 0; k < 18; k++) {
                    float4 pp = __ldcg((const float4*)(PART + (size_t)k * HB + off));
                    s4.x += pp.x; s4.y += pp.y; s4.z += pp.z; s4.w += pp.w;
                }
                const int n = (int)(off >> 7);
                const float bb = b1x[n] + b1r[n];
                __stcg((float4*)(D1 + off),
                       make_float4(SCALE * (s4.x + bb), SCALE * (s4.y + bb),
                                   SCALE * (s4.z + bb), SCALE * (s4.w + bb)));
            }
        }
        grid_bar(gen);

        // ---- P3: tau1 partials (K=2048 = 128 tiles; 16nt x 8s x 2z) ----
        if (bid < 256) {
            const int nt = bid & 15, s = (bid >> 4) & 7, z = bid >> 7;
            gemm_job(D1, z ? STQ(p, BB1) : STQ(p, MEM1), 64,
                     z ? w1a : w1m, 2 * H, s * 16, s * 16 + 16, nt * NT,
                     PARTMA + (size_t)(z * 8 + s) * HB, Abuf, Wbuf);
        }
        grid_bar(gen);

        // ---- P4: tau1 reduce + adaptive update -> parity q ----
        {
            const int idx = bid * 256 + tid;
            if (idx < (int)(HB / 4)) {
                const size_t off = (size_t)idx * 4;
                float4 sm = make_float4(0.f, 0.f, 0.f, 0.f);
                float4 sa = make_float4(0.f, 0.f, 0.f, 0.f);
                for (int k = 0; k < 8; k++) {
                    float4 pm = __ldcg((const float4*)(PARTMA + (size_t)k * HB + off));
                    float4 pa = __ldcg((const float4*)(PARTMA + (size_t)(8 + k) * HB + off));
                    sm.x += pm.x; sm.y += pm.y; sm.z += pm.z; sm.w += pm.w;
                    sa.x += pa.x; sa.y += pa.y; sa.z += pa.z; sa.w += pa.w;
                }
                const int n = (int)(off >> 7);
                const float bmo = b1m[n], bao = b1a[n];
                float4 dn = __ldcg((const float4*)(D1 + off));
                float4 me = __ldcg((const float4*)(STQ(p, MEM1) + off));
                float4 bo = __ldcg((const float4*)(STQ(p, BB1) + off));
                float4 sp = __ldcg((const float4*)(STQ(p, SPK1) + off));
                float tmv[4] = { sigmf(sm.x+bmo), sigmf(sm.y+bmo), sigmf(sm.z+bmo), sigmf(sm.w+bmo) };
                float tav[4] = { sigmf(sa.x+bao), sigmf(sa.y+bao), sigmf(sa.z+bao), sigmf(sa.w+bao) };
                float dv[4] = { dn.x, dn.y, dn.z, dn.w };
                float mv[4] = { me.x, me.y, me.z, me.w };
                float bv[4] = { bo.x, bo.y, bo.z, bo.w };
                float sv[4] = { sp.x, sp.y, sp.z, sp.w };
                float nm[4], ns[4], nb[4];
                #pragma unroll
                for (int j = 0; j < 4; j++) {
                    float bn  = tav[j] * bv[j] + (1.0f - tav[j]) * sv[j];
                    float Bth = 0.1f + 1.8f * bn;
                    float mn  = mv[j] + (dv[j] - mv[j]) * tmv[j];
                    float s   = (mn - Bth) > 0.0f ? 1.0f : 0.0f;
                    nm[j] = (1.0f - s) * mn; ns[j] = s; nb[j] = bn;
                }
                __stcg((float4*)(STQ(q, MEM1) + off), make_float4(nm[0], nm[1], nm[2], nm[3]));
                __stcg((float4*)(STQ(q, SPK1) + off), make_float4(ns[0], ns[1], ns[2], ns[3]));
                __stcg((float4*)(STQ(q, BB1)  + off), make_float4(nb[0], nb[1], nb[2], nb[3]));
            }
        }
        grid_bar(gen);

        // ---- P5: dense2 partials (K=2048=128 tiles, 18 splits) ----
        if (bid < 288) {
            const int nt = bid & 15, s = bid >> 4;
            const int tbgn = (128 * s) / 18, tend = (128 * (s + 1)) / 18;
            gemm_job(STQ(q, SPK1), STQ(p, SPK1), 64, W2C, 2 * H,
                     tbgn, tend, nt * NT, PART + (size_t)s * HB, Abuf, Wbuf);
        }
        grid_bar(gen);

        // ---- P6: reduce D2 ----
        {
            const int idx = bid * 256 + tid;
            if (idx < (int)(HB / 4)) {
                const size_t off = (size_t)idx * 4;
                float4 s4 = make_float4(0.f, 0.f, 0.f, 0.f);
                for (int k = 0; k < 18; k++) {
                    float4 pp = __ldcg((const float4*)(PART + (size_t)k * HB + off));
                    s4.x += pp.x; s4.y += pp.y; s4.z += pp.z; s4.w += pp.w;
                }
                const int n = (int)(off >> 7);
                const float bb = b2x[n] + b2r[n];
                __stcg((float4*)(D2 + off),
                       make_float4(SCALE * (s4.x + bb), SCALE * (s4.y + bb),
                                   SCALE * (s4.z + bb), SCALE * (s4.w + bb)));
            }
        }
        grid_bar(gen);

        // ---- P7: tau2 partials ----
        if (bid < 256) {
            const int nt = bid & 15, s = (bid >> 4) & 7, z = bid >> 7;
            gemm_job(D2, z ? STQ(p, BB2) : STQ(p, MEM2), 64,
                     z ? w2a : w2m, 2 * H, s * 16, s * 16 + 16, nt * NT,
                     PARTMA + (size_t)(z * 8 + s) * HB, Abuf, Wbuf);
        }
        grid_bar(gen);

        // ---- P8: tau2 reduce + update -> parity q ----
        {
            const int idx = bid * 256 + tid;
            if (idx < (int)(HB / 4)) {
                const size_t off = (size_t)idx * 4;
                float4 sm = make_float4(0.f, 0.f, 0.f, 0.f);
                float4 sa = make_float4(0.f, 0.f, 0.f, 0.f);
                for (int k = 0; k < 8; k++) {
                    float4 pm = __ldcg((const float4*)(PARTMA + (size_t)k * HB + off));
                    float4 pa = __ldcg((const float4*)(PARTMA + (size_t)(8 + k) * HB + off));
                    sm.x += pm.x; sm.y += pm.y; sm.z += pm.z; sm.w += pm.w;
                    sa.x += pa.x; sa.y += pa.y; sa.z += pa.z; sa.w += pa.w;
                }
                const int n = (int)(off >> 7);
                const float bmo = b2m[n], bao = b2a[n];
                float4 dn = __ldcg((const float4*)(D2 + off));
                float4 me = __ldcg((const float4*)(STQ(p, MEM2) + off));
                float4 bo = __ldcg((const float4*)(STQ(p, BB2) + off));
                float4 sp = __ldcg((const float4*)(STQ(p, SPK2) + off));
                float tmv[4] = { sigmf(sm.x+bmo), sigmf(sm.y+bmo), sigmf(sm.z+bmo), sigmf(sm.w+bmo) };
                float tav[4] = { sigmf(sa.x+bao), sigmf(sa.y+bao), sigmf(sa.z+bao), sigmf(sa.w+bao) };
                float dv[4] = { dn.x, dn.y, dn.z, dn.w };
                float mv[4] = { me.x, me.y, me.z, me.w };
                float bv[4] = { bo.x, bo.y, bo.z, bo.w };
                float sv[4] = { sp.x, sp.y, sp.z, sp.w };
                float nm[4], ns[4], nb[4];
                #pragma unroll
                for (int j = 0; j < 4; j++) {
                    float bn  = tav[j] * bv[j] + (1.0f - tav[j]) * sv[j];
                    float Bth = 0.1f + 1.8f * bn;
                    float mn  = mv[j] + (dv[j] - mv[j]) * tmv[j];
                    float s   = (mn - Bth) > 0.0f ? 1.0f : 0.0f;
                    nm[j] = (1.0f - s) * mn; ns[j] = s; nb[j] = bn;
                }
                __stcg((float4*)(STQ(q, MEM2) + off), make_float4(nm[0], nm[1], nm[2], nm[3]));
                __stcg((float4*)(STQ(q, SPK2) + off), make_float4(ns[0], ns[1], ns[2], ns[3]));
                __stcg((float4*)(STQ(q, BB2)  + off), make_float4(nb[0], nb[1], nb[2], nb[3]));
            }
        }
        grid_bar(gen);

        // ---- P9a: head GEMM, 20 blocks (class = bid), K=1024 ----
        if (bid < 20) {
            const int warp = tid >> 5, lane = tid & 31;
            const int o = bid;
            const float* A = STQ(q, SPK2) + (size_t)(warp * 128) * B + lane * 4;
            const float* Wr = w3x + (size_t)o * H + warp * 128;
            float a0 = 0.f, a1 = 0.f, a2 = 0.f, a3 = 0.f;
            #pragma unroll 4
            for (int k = 0; k < 128; k++) {
                float4 av = __ldcg((const float4*)(A + (size_t)k * B));
                float wv = Wr[k];
                a0 += av.x * wv; a1 += av.y * wv; a2 += av.z * wv; a3 += av.w * wv;
            }
            float* red = smem;              // [8][128] scratch (4 KB)
            red[warp * B + lane * 4 + 0] = a0;
            red[warp * B + lane * 4 + 1] = a1;
            red[warp * B + lane * 4 + 2] = a2;
            red[warp * B + lane * 4 + 3] = a3;
            __syncthreads();
            if (tid < B) {
                float s = 0.f;
                #pragma unroll
                for (int w = 0; w < 8; w++) s += red[w * B + tid];
                __stcg(D3 + o * B + tid, SCALE * (s + b3x[o]));
            }
            __syncthreads();
        }
        grid_bar(gen);

        // ---- P9b: final blend + log-softmax (block 0 only; no barrier,
        //      covered by next step's P1 barrier) ----
        if (bid == 0 && tid < B) {
            const int b = tid;
            float d3v[O], m3v[O], nm[O];
            #pragma unroll
            for (int k = 0; k < O; k++) {
                d3v[k] = __ldcg(D3 + k * B + b);
                m3v[k] = __ldcg(M3 + (size_t)p * O * B + k * B + b);
            }
            #pragma unroll
            for (int o = 0; o < O; o++) {
                const float* w = w3m + o * (2 * O);
                float acc = b3m[o];
                #pragma unroll
                for (int k = 0; k < O; k++) acc += d3v[k] * w[k];
                #pragma unroll
                for (int k = 0; k < O; k++) acc += m3v[k] * w[O + k];
                float tm = sigmf(acc);
                float v = (1.0f - tm) * m3v[o] + d3v[o] * tm;
                nm[o] = v;
                __stcg(M3 + (size_t)q * O * B + o * B + b, v);
            }
            float mx = nm[0];
            #pragma unroll
            for (int o = 1; o < O; o++) mx = fmaxf(mx, nm[o]);
            float s = 0.f;
            #pragma unroll
            for (int o = 0; o < O; o++) s += expf(nm[o] - mx);
            float lse = logf(s);
            #pragma unroll
            for (int o = 0; o < O; o++) out[(size_t)t * B * O + b * O + o] = nm[o] - mx - lse;
        }
    }
    #undef STQ
}

// ---------------------------------------------------------------------------
// Pre/post kernels
// ---------------------------------------------------------------------------
__global__ void init_bar_k() {
    if (threadIdx.x == 0) { g_arrive = 0u; g_phase = 0u; }
}

__global__ void transpose_x_k(const float* __restrict__ in, float* __restrict__ out)
{
    __shared__ float tile[32][33];
    const int t = blockIdx.z;
    const int i0 = blockIdx.x * 32, b0 = blockIdx.y * 32;
    for (int r = threadIdx.y; r < 32; r += 8) {
        int bb = b0 + r, i = i0 + threadIdx.x;
        tile[r][threadIdx.x] = (i < DIN) ? in[(size_t)bb * T * DIN + (size_t)t * DIN + i] : 0.0f;
    }
    __syncthreads();
    for (int r = threadIdx.y; r < 32; r += 8) {
        int i = i0 + r, bb = b0 + threadIdx.x;
        out[((size_t)t * DINP + i) * B + bb] = tile[threadIdx.x][r];
    }
}

__global__ void tr_in_k(const float* __restrict__ in, float* __restrict__ st, int F)
{
    __shared__ float tile[32][33];
    const int j0 = blockIdx.x * 32, b0 = blockIdx.y * 32;
    for (int r = threadIdx.y; r < 32; r += 8) {
        int bb = b0 + r, j = j0 + threadIdx.x;
        tile[r][threadIdx.x] = (j < F) ? in[(size_t)bb * F + j] : 0.0f;
    }
    __syncthreads();
    for (int r = threadIdx.y; r < 32; r += 8) {
        int j = j0 + r, bb = b0 + threadIdx.x;
        if (j < F) st[(size_t)j * B + bb] = tile[threadIdx.x][r];
    }
}

__global__ void tr_out_k(const float* __restrict__ st, float* __restrict__ out, int F)
{
    __shared__ float tile[32][33];
    const int j0 = blockIdx.x * 32, b0 = blockIdx.y * 32;
    for (int r = threadIdx.y; r < 32; r += 8) {
        int j = j0 + r, bb = b0 + threadIdx.x;
        tile[r][threadIdx.x] = (j < F) ? st[(size_t)j * B + bb] : 0.0f;
    }
    __syncthreads();
    for (int r = threadIdx.y; r < 32; r += 8) {
        int bb = b0 + r, j = j0 + threadIdx.x;
        if (j < F) out[(size_t)bb * F + j] = tile[threadIdx.x][r];
    }
}

__global__ void catW1_k(const float* __restrict__ w1x, const float* __restrict__ w1r,
                        float* __restrict__ Wcat)
{
    int idx = blockIdx.x * 256 + threadIdx.x;
    if (idx >= H * (DINP + H)) return;
    int n = idx / (DINP + H), c = idx % (DINP + H);
    float v;
    if (c < DINP) v = (c < DIN) ? w1x[(size_t)n * DIN + c] : 0.0f;
    else          v = w1r[(size_t)n * H + (c - DINP)];
    Wcat[idx] = v;
}

__global__ void catW2_k(const float* __restrict__ w2x, const float* __restrict__ w2r,
                        float* __restrict__ Wcat)
{
    int idx = blockIdx.x * 256 + threadIdx.x;
    if (idx >= H * 2 * H) return;
    int n = idx / (2 * H), c = idx % (2 * H);
    Wcat[idx] = (c < H) ? w2x[(size_t)n * H + c] : w2r[(size_t)n * H + (c - H)];
}

// ---------------------------------------------------------------------------
extern "C" void kernel_launch(void* const* d_in, const int* in_sizes, int n_in,
                              void* d_out, int out_size)
{
    (void)in_sizes; (void)n_in; (void)out_size;
    const float* inputs = (const float*)d_in[0];
    const float* h[7];
    for (int i = 0; i < 7; i++) h[i] = (const float*)d_in[1 + i];
    const float* w1x = (const float*)d_in[8];  const float* b1x = (const float*)d_in[9];
    const float* w1r = (const float*)d_in[10]; const float* b1r = (const float*)d_in[11];
    const float* w1m = (const float*)d_in[12]; const float* b1m = (const float*)d_in[13];
    const float* w1a = (const float*)d_in[14]; const float* b1a = (const float*)d_in[15];
    const float* w2x = (const float*)d_in[16]; const float* b2x = (const float*)d_in[17];
    const float* w2r = (const float*)d_in[18]; const float* b2r = (const float*)d_in[19];
    const float* w2m = (const float*)d_in[20]; const float* b2m = (const float*)d_in[21];
    const float* w2a = (const float*)d_in[22]; const float* b2a = (const float*)d_in[23];
    const float* w3x = (const float*)d_in[24]; const float* b3x = (const float*)d_in[25];
    const float* w3m = (const float*)d_in[26]; const float* b3m = (const float*)d_in[27];
    float* out = (float*)d_out;

    float *XT, *ST, *M3, *D1, *D2, *D3, *PART, *PARTMA, *W1C, *W2C;
    cudaGetSymbolAddress((void**)&XT, g_XT);
    cudaGetSymbolAddress((void**)&ST, g_state);
    cudaGetSymbolAddress((void**)&M3, g_m3);
    cudaGetSymbolAddress((void**)&D1, g_d1);
    cudaGetSymbolAddress((void**)&D2, g_d2);
    cudaGetSymbolAddress((void**)&D3, g_d3);
    cudaGetSymbolAddress((void**)&PART, g_part);
    cudaGetSymbolAddress((void**)&PARTMA, g_partMA);
    cudaGetSymbolAddress((void**)&W1C, g_W1cat);
    cudaGetSymbolAddress((void**)&W2C, g_W2cat);

    const size_t HB = (size_t)H * B;
    #define STP(p, s) (ST + ((size_t)(p) * 6 + (s)) * HB)

    dim3 tb(32, 8);
    transpose_x_k<<<dim3(22, 4, T), tb>>>(inputs, XT);
    catW1_k<<<(H * (DINP + H) + 255) / 256, 256>>>(w1x, w1r, W1C);
    catW2_k<<<(H * 2 * H + 255) / 256, 256>>>(w2x, w2r, W2C);
    for (int s = 0; s < 6; s++)
        tr_in_k<<<dim3(32, 4), tb>>>(h[s], STP(0, s), H);
    tr_in_k<<<dim3(1, 4), tb>>>(h[6], M3, O);
    init_bar_k<<<1, 32>>>();

    snn_persist_k<<<NBLK, 256>>>(
        XT, W1C, W2C,
        b1x, b1r, w1m, b1m, w1a, b1a,
        b2x, b2r, w2m, b2m, w2a, b2a,
        w3x, b3x, w3m, b3m,
        ST, M3, D1, D2, D3, PART, PARTMA, out);

    float* tail = out + (size_t)T * B * O;
    for (int s = 0; s < 6; s++)
        tr_out_k<<<dim3(32, 4), tb>>>(STP(0, s), tail + (size_t)s * HB, H);
    tr_out_k<<<dim3(1, 4), tb>>>(M3, tail + 6 * HB, O);
}

// round 11
// speedup vs baseline: 1.6144x; 1.6144x over previous
#include <cuda_runtime.h>
#include <cuda_fp16.h>
#include <cstddef>

// ===========================================================================
// SNN forward: persistent kernel; warp-level mma.sync.m16n8k16 (HMMA) with
// fp16 hi/lo splitting. Batch-major everywhere. fp16 operand tiles stored in
// global as linear [chunk][row(128)][64 halves]; blocks cp.async them into
// SW128-swizzled smem; A(M)=activation(batch), B(N)=weights(neuron).
// ===========================================================================

#define B     128
#define T     100
#define DIN   700
#define H     1024
#define O     20
#define NBLK  128
#define SCALE 0.09999950000374997f   // 0.1/sqrt(1+1e-5)
#define TILE  8192                   // halves per 128x64 tile
#define T8    (8 * TILE)             // halves per chunk across 8 mtiles
#define BH    (B * H)

enum { MEM1 = 0, SPK1, BB1, MEM2, SPK2, BB2 };

// ---- fp16 images ----
__device__ __half g_xh[(size_t)T * 11 * TILE], g_xl[(size_t)T * 11 * TILE];
__device__ __half g_wd1[(size_t)65 * T8], g_wd2[(size_t)64 * T8];
__device__ __half g_wt1m[(size_t)96 * T8], g_wt1a[(size_t)96 * T8];
__device__ __half g_wt2m[(size_t)96 * T8], g_wt2a[(size_t)96 * T8];
__device__ __half g_spk1i[2][16 * TILE];
__device__ __half g_m1h[2][16 * TILE], g_m1l[2][16 * TILE];
__device__ __half g_b1h[2][16 * TILE], g_b1l[2][16 * TILE];
__device__ __half g_m2h[2][16 * TILE], g_m2l[2][16 * TILE];
__device__ __half g_b2h[2][16 * TILE], g_b2l[2][16 * TILE];
__device__ __half g_d1h[16 * TILE], g_d1l[16 * TILE];
__device__ __half g_d2h[16 * TILE], g_d2l[16 * TILE];
// ---- fp32 state/scratch (batch-major [b][n]) ----
__device__ float g_st[12 * BH];              // [parity][6][BH]
__device__ float g_m3[2 * B * O];
__device__ float g_d1[BH], g_d2[BH];
__device__ float g_part[16 * BH];
__device__ float g_pma[16 * BH];             // [z*8+s][BH]
__device__ unsigned g_arrive, g_phasec;

// ---------------------------------------------------------------------------
__device__ __forceinline__ float sigmf(float x) { return 1.0f / (1.0f + expf(-x)); }
#define SW128(o) ((o) ^ (((o) >> 3) & 0x70))

__device__ __forceinline__ void cpa16(void* dst_smem, const void* src) {
    unsigned d = (unsigned)__cvta_generic_to_shared(dst_smem);
    asm volatile("cp.async.cg.shared.global [%0], [%1], 16;\n" :: "r"(d), "l"(src));
}
__device__ __forceinline__ void cpa_commit() {
    asm volatile("cp.async.commit_group;\n" ::: "memory");
}
__device__ __forceinline__ void cpa_wait0() {
    asm volatile("cp.async.wait_group 0;\n" ::: "memory");
}
__device__ __forceinline__ unsigned smem_u32(const void* p) {
    return (unsigned)__cvta_generic_to_shared(p);
}
__device__ __forceinline__ void ldsm4(unsigned* r, unsigned addr) {
    asm volatile("ldmatrix.sync.aligned.m8n8.x4.shared.b16 {%0,%1,%2,%3}, [%4];"
        : "=r"(r[0]), "=r"(r[1]), "=r"(r[2]), "=r"(r[3]) : "r"(addr));
}
__device__ __forceinline__ void mma16816(float* d, const unsigned* a,
                                         unsigned b0, unsigned b1) {
    asm volatile(
        "mma.sync.aligned.m16n8k16.row.col.f32.f16.f16.f32 "
        "{%0,%1,%2,%3}, {%4,%5,%6,%7}, {%8,%9}, {%0,%1,%2,%3};"
        : "+f"(d[0]), "+f"(d[1]), "+f"(d[2]), "+f"(d[3])
        : "r"(a[0]), "r"(a[1]), "r"(a[2]), "r"(a[3]), "r"(b0), "r"(b1));
}

__device__ __forceinline__ void grid_bar(unsigned& gen) {
    __syncthreads();
    if (threadIdx.x == 0) {
        __threadfence();
        unsigned t = atomicAdd(&g_arrive, 1u);
        if (t == NBLK - 1) {
            *(volatile unsigned*)&g_arrive = 0u;
            __threadfence();
            atomicAdd(&g_phasec, 1u);
        } else {
            volatile unsigned* ph = &g_phasec;
            while (*ph == gen) { __nanosleep(64); }
            __threadfence();
        }
    }
    __syncthreads();
    gen++;
}

__device__ __forceinline__ unsigned packh(__half a, __half b) {
    __half2 t = __halves2half2(a, b);
    return *(unsigned*)&t;
}
// write fp16 images (hi, optional lo) for 4 consecutive n at (b, n)
__device__ __forceinline__ void wr_img(__half* hi, __half* lo, int n, int b, float4 v) {
    int ii = (n >> 6) * TILE + b * 64 + (n & 63);
    __half h0 = __float2half_rn(v.x), h1 = __float2half_rn(v.y);
    __half h2 = __float2half_rn(v.z), h3 = __float2half_rn(v.w);
    __stcg((uint2*)(hi + ii), make_uint2(packh(h0, h1), packh(h2, h3)));
    if (lo) {
        __half l0 = __float2half_rn(v.x - __half2float(h0));
        __half l1 = __float2half_rn(v.y - __half2float(h1));
        __half l2 = __float2half_rn(v.z - __half2float(h2));
        __half l3 = __float2half_rn(v.w - __half2float(h3));
        __stcg((uint2*)(lo + ii), make_uint2(packh(l0, l1), packh(l2, l3)));
    }
}

// ---------------------------------------------------------------------------
// A-operand (activation) tile resolver. stage: 0=dense1, 1=dense2, 2=tau1, 3=tau2
// ---------------------------------------------------------------------------
__device__ __forceinline__ const __half* resolve_A(int stage, int z, int c, int t, int p) {
    if (stage == 0) {
        if (c < 33) {
            int idx = (c < 11) ? c : (c < 22 ? c - 11 : c - 22);
            const __half* base = (c >= 11 && c < 22) ? g_xl : g_xh;
            return base + ((size_t)t * 11 + idx) * TILE;
        }
        return g_spk1i[p] + (size_t)((c - 33) & 15) * TILE;
    }
    if (stage == 1) {
        int sub = c >> 4, cc = c & 15;
        return g_spk1i[sub < 2 ? (p ^ 1) : p] + (size_t)cc * TILE;
    }
    int sub = c >> 4, cc = c & 15, l = stage - 2;
    const __half* base;
    if (sub < 3) {
        base = (sub == 1) ? (l ? g_d2l : g_d1l) : (l ? g_d2h : g_d1h);
    } else {
        int s2 = sub - 3;
        if (!z) base = (s2 == 1) ? (l ? g_m2l[p] : g_m1l[p]) : (l ? g_m2h[p] : g_m1h[p]);
        else    base = (s2 == 1) ? (l ? g_b2l[p] : g_b1l[p]) : (l ? g_b2h[p] : g_b1h[p]);
    }
    return base + (size_t)cc * TILE;
}

// ---------------------------------------------------------------------------
// GEMM job via mma.sync: chunks [tb,te) -> partial[b][mt*128..+128].
// dsm: 2 x 32KB buffers (A act tile 16KB + W tile 16KB each).
// Warp grid: 4 m-quadrants (batch, 32 rows) x 2 n-halves (neuron, 64 cols).
// ---------------------------------------------------------------------------
__device__ void mma_run(const __half* Wimg, int stage, int z, int t, int p, int mt,
                        int tb, int te, float* __restrict__ partial, char* dsm)
{
    const int tid = threadIdx.x;
    const int warp = tid >> 5, lane = tid & 31;
    const int wm = warp >> 1;    // batch quadrant
    const int wn = warp & 1;     // neuron half
    const int nb = te - tb;

    float acc[16][4];
    #pragma unroll
    for (int i = 0; i < 16; i++)
        acc[i][0] = acc[i][1] = acc[i][2] = acc[i][3] = 0.f;

    auto load_tile = [&](int c, int buf) {
        const char* ap = (const char*)resolve_A(stage, z, c, t, p);
        const char* wp = (const char*)(Wimg + ((size_t)c * 8 + mt) * TILE);
        char* ad = dsm + buf * 32768;
        char* wd = ad + 16384;
        #pragma unroll
        for (int i = 0; i < 4; i++) {
            int off = (tid + i * 256) * 16;
            int sw = SW128(off);
            cpa16(ad + sw, ap + off);
            cpa16(wd + sw, wp + off);
        }
        cpa_commit();
    };

    load_tile(tb, 0);
    for (int i = 0; i < nb; i++) {
        cpa_wait0();
        __syncthreads();                 // buffer i ready; compute i-1 done
        if (i + 1 < nb) load_tile(tb + i + 1, (i + 1) & 1);   // overlaps compute
        const char* ad = dsm + (i & 1) * 32768;
        const char* wd = ad + 16384;
        const unsigned ab = smem_u32(ad), wb = smem_u32(wd);

        #pragma unroll
        for (int ks = 0; ks < 4; ks++) {
            unsigned a0[4], a1[4];
            {
                int row = wm * 32 + (lane & 7) + ((lane >> 3) & 1) * 8;
                int kb = ks * 32 + (lane >> 4) * 16;
                ldsm4(a0, ab + SW128(row * 128 + kb));
                ldsm4(a1, ab + SW128((row + 16) * 128 + kb));
            }
            unsigned bf[4][4];
            #pragma unroll
            for (int nf = 0; nf < 4; nf++) {
                int nr = wn * 64 + nf * 16 + (lane & 7) + ((lane >> 4) & 1) * 8;
                int kb = ks * 32 + ((lane >> 3) & 1) * 16;
                ldsm4(bf[nf], wb + SW128(nr * 128 + kb));
            }
            #pragma unroll
            for (int nf = 0; nf < 4; nf++) {
                mma16816(acc[nf * 2 + 0],     a0, bf[nf][0], bf[nf][1]);
                mma16816(acc[nf * 2 + 1],     a0, bf[nf][2], bf[nf][3]);
                mma16816(acc[8 + nf * 2 + 0], a1, bf[nf][0], bf[nf][1]);
                mma16816(acc[8 + nf * 2 + 1], a1, bf[nf][2], bf[nf][3]);
            }
        }
    }
    __syncthreads();

    // epilogue: acc -> partial[b][mt*128 + n], coalesced-ish v2 stores
    const int ncol0 = mt * 128 + wn * 64 + (lane & 3) * 2;
    #pragma unroll
    for (int mf = 0; mf < 2; mf++) {
        const int row0 = wm * 32 + mf * 16 + (lane >> 2);
        #pragma unroll
        for (int n8 = 0; n8 < 8; n8++) {
            float* p0 = partial + (size_t)row0 * H + ncol0 + n8 * 8;
            float* p1 = partial + (size_t)(row0 + 8) * H + ncol0 + n8 * 8;
            __stcg((float2*)p0, make_float2(acc[mf * 8 + n8][0], acc[mf * 8 + n8][1]));
            __stcg((float2*)p1, make_float2(acc[mf * 8 + n8][2], acc[mf * 8 + n8][3]));
        }
    }
}

// ---------------------------------------------------------------------------
// persistent kernel
// ---------------------------------------------------------------------------
__global__ void __launch_bounds__(256) snn_persist_k(
    const float* __restrict__ b1x, const float* __restrict__ b1r,
    const float* __restrict__ b1m, const float* __restrict__ b1a,
    const float* __restrict__ b2x, const float* __restrict__ b2r,
    const float* __restrict__ b2m, const float* __restrict__ b2a,
    const float* __restrict__ w3x, const float* __restrict__ b3x,
    const float* __restrict__ w3m, const float* __restrict__ b3m,
    float* __restrict__ out)
{
    extern __shared__ __align__(1024) char dsm[];   // 64 KB dynamic

    const int bid = blockIdx.x, tid = threadIdx.x;
    unsigned gen = 0;

    #define STQ(pp, ss) (g_st + ((size_t)(pp) * 6 + (ss)) * BH)

    for (int t = 0; t < T; t++) {
        const int p = t & 1, q = p ^ 1;

        // ---- P1: dense1 MMA (65 chunks; 8 mt x 16 splits) ----
        {
            const int mt = bid & 7, s = bid >> 3;
            mma_run(g_wd1, 0, 0, t, p, mt, (65 * s) / 16, (65 * (s + 1)) / 16,
                    g_part + (size_t)s * BH, dsm);
        }
        grid_bar(gen);

        // ---- P2: reduce D1 (16 slices) + D1 images ----
        {
            const size_t off = ((size_t)bid * 256 + tid) * 4;
            float4 s4 = make_float4(0.f, 0.f, 0.f, 0.f);
            #pragma unroll
            for (int k = 0; k < 16; k++) {
                float4 pp = __ldcg((const float4*)(g_part + (size_t)k * BH + off));
                s4.x += pp.x; s4.y += pp.y; s4.z += pp.z; s4.w += pp.w;
            }
            const int b = (int)(off >> 10), n = (int)(off & 1023);
            float4 bx = *(const float4*)(b1x + n), br = *(const float4*)(b1r + n);
            float4 r = make_float4(SCALE * (s4.x + bx.x + br.x), SCALE * (s4.y + bx.y + br.y),
                                   SCALE * (s4.z + bx.z + br.z), SCALE * (s4.w + bx.w + br.w));
            __stcg((float4*)(g_d1 + off), r);
            wr_img(g_d1h, g_d1l, n, b, r);
        }
        grid_bar(gen);

        // ---- P3: tau1 MMA (96 chunks per z; 8mt x 8s x 2z) ----
        {
            const int mt = bid & 7, s = (bid >> 3) & 7, z = bid >> 6;
            mma_run(z ? g_wt1a : g_wt1m, 2, z, t, p, mt, s * 12, s * 12 + 12,
                    g_pma + (size_t)(z * 8 + s) * BH, dsm);
        }
        grid_bar(gen);

        // ---- P4: tau1 reduce + adaptive update -> parity q (+ images[q]) ----
        {
            const size_t off = ((size_t)bid * 256 + tid) * 4;
            float4 sm = make_float4(0.f, 0.f, 0.f, 0.f), sa = sm;
            #pragma unroll
            for (int k = 0; k < 8; k++) {
                float4 pm = __ldcg((const float4*)(g_pma + (size_t)k * BH + off));
                float4 pa = __ldcg((const float4*)(g_pma + (size_t)(8 + k) * BH + off));
                sm.x += pm.x; sm.y += pm.y; sm.z += pm.z; sm.w += pm.w;
                sa.x += pa.x; sa.y += pa.y; sa.z += pa.z; sa.w += pa.w;
            }
            const int b = (int)(off >> 10), n = (int)(off & 1023);
            float4 bm4 = *(const float4*)(b1m + n), ba4 = *(const float4*)(b1a + n);
            float4 dn = __ldcg((const float4*)(g_d1 + off));
            float4 me = __ldcg((const float4*)(STQ(p, MEM1) + off));
            float4 bo = __ldcg((const float4*)(STQ(p, BB1) + off));
            float4 sp = __ldcg((const float4*)(STQ(p, SPK1) + off));
            float tm[4] = { sigmf(sm.x + bm4.x), sigmf(sm.y + bm4.y),
                            sigmf(sm.z + bm4.z), sigmf(sm.w + bm4.w) };
            float ta[4] = { sigmf(sa.x + ba4.x), sigmf(sa.y + ba4.y),
                            sigmf(sa.z + ba4.z), sigmf(sa.w + ba4.w) };
            float dv[4] = { dn.x, dn.y, dn.z, dn.w }, mv[4] = { me.x, me.y, me.z, me.w };
            float bv[4] = { bo.x, bo.y, bo.z, bo.w }, sv[4] = { sp.x, sp.y, sp.z, sp.w };
            float nm[4], ns[4], nb[4];
            #pragma unroll
            for (int j = 0; j < 4; j++) {
                float bn = ta[j] * bv[j] + (1.0f - ta[j]) * sv[j];
                float mn = mv[j] + (dv[j] - mv[j]) * tm[j];
                float s = (mn - (0.1f + 1.8f * bn)) > 0.0f ? 1.0f : 0.0f;
                nm[j] = (1.0f - s) * mn; ns[j] = s; nb[j] = bn;
            }
            float4 fm = make_float4(nm[0], nm[1], nm[2], nm[3]);
            float4 fs = make_float4(ns[0], ns[1], ns[2], ns[3]);
            float4 fb = make_float4(nb[0], nb[1], nb[2], nb[3]);
            __stcg((float4*)(STQ(q, MEM1) + off), fm);
            __stcg((float4*)(STQ(q, SPK1) + off), fs);
            __stcg((float4*)(STQ(q, BB1) + off), fb);
            wr_img(g_m1h[q], g_m1l[q], n, b, fm);
            wr_img(g_spk1i[q], 0, n, b, fs);
            wr_img(g_b1h[q], g_b1l[q], n, b, fb);
        }
        grid_bar(gen);

        // ---- P5: dense2 MMA (64 chunks; 8 mt x 16 splits) ----
        {
            const int mt = bid & 7, s = bid >> 3;
            mma_run(g_wd2, 1, 0, t, p, mt, s * 4, s * 4 + 4,
                    g_part + (size_t)s * BH, dsm);
        }
        grid_bar(gen);

        // ---- P6: reduce D2 + images ----
        {
            const size_t off = ((size_t)bid * 256 + tid) * 4;
            float4 s4 = make_float4(0.f, 0.f, 0.f, 0.f);
            #pragma unroll
            for (int k = 0; k < 16; k++) {
                float4 pp = __ldcg((const float4*)(g_part + (size_t)k * BH + off));
                s4.x += pp.x; s4.y += pp.y; s4.z += pp.z; s4.w += pp.w;
            }
            const int b = (int)(off >> 10), n = (int)(off & 1023);
            float4 bx = *(const float4*)(b2x + n), br = *(const float4*)(b2r + n);
            float4 r = make_float4(SCALE * (s4.x + bx.x + br.x), SCALE * (s4.y + bx.y + br.y),
                                   SCALE * (s4.z + bx.z + br.z), SCALE * (s4.w + bx.w + br.w));
            __stcg((float4*)(g_d2 + off), r);
            wr_img(g_d2h, g_d2l, n, b, r);
        }
        grid_bar(gen);

        // ---- P7: tau2 MMA ----
        {
            const int mt = bid & 7, s = (bid >> 3) & 7, z = bid >> 6;
            mma_run(z ? g_wt2a : g_wt2m, 3, z, t, p, mt, s * 12, s * 12 + 12,
                    g_pma + (size_t)(z * 8 + s) * BH, dsm);
        }
        grid_bar(gen);

        // ---- P8: tau2 reduce + update -> parity q ----
        {
            const size_t off = ((size_t)bid * 256 + tid) * 4;
            float4 sm = make_float4(0.f, 0.f, 0.f, 0.f), sa = sm;
            #pragma unroll
            for (int k = 0; k < 8; k++) {
                float4 pm = __ldcg((const float4*)(g_pma + (size_t)k * BH + off));
                float4 pa = __ldcg((const float4*)(g_pma + (size_t)(8 + k) * BH + off));
                sm.x += pm.x; sm.y += pm.y; sm.z += pm.z; sm.w += pm.w;
                sa.x += pa.x; sa.y += pa.y; sa.z += pa.z; sa.w += pa.w;
            }
            const int b = (int)(off >> 10), n = (int)(off & 1023);
            float4 bm4 = *(const float4*)(b2m + n), ba4 = *(const float4*)(b2a + n);
            float4 dn = __ldcg((const float4*)(g_d2 + off));
            float4 me = __ldcg((const float4*)(STQ(p, MEM2) + off));
            float4 bo = __ldcg((const float4*)(STQ(p, BB2) + off));
            float4 sp = __ldcg((const float4*)(STQ(p, SPK2) + off));
            float tm[4] = { sigmf(sm.x + bm4.x), sigmf(sm.y + bm4.y),
                            sigmf(sm.z + bm4.z), sigmf(sm.w + bm4.w) };
            float ta[4] = { sigmf(sa.x + ba4.x), sigmf(sa.y + ba4.y),
                            sigmf(sa.z + ba4.z), sigmf(sa.w + ba4.w) };
            float dv[4] = { dn.x, dn.y, dn.z, dn.w }, mv[4] = { me.x, me.y, me.z, me.w };
            float bv[4] = { bo.x, bo.y, bo.z, bo.w }, sv[4] = { sp.x, sp.y, sp.z, sp.w };
            float nm[4], ns[4], nb[4];
            #pragma unroll
            for (int j = 0; j < 4; j++) {
                float bn = ta[j] * bv[j] + (1.0f - ta[j]) * sv[j];
                float mn = mv[j] + (dv[j] - mv[j]) * tm[j];
                float s = (mn - (0.1f + 1.8f * bn)) > 0.0f ? 1.0f : 0.0f;
                nm[j] = (1.0f - s) * mn; ns[j] = s; nb[j] = bn;
            }
            float4 fm = make_float4(nm[0], nm[1], nm[2], nm[3]);
            float4 fs = make_float4(ns[0], ns[1], ns[2], ns[3]);
            float4 fb = make_float4(nb[0], nb[1], nb[2], nb[3]);
            __stcg((float4*)(STQ(q, MEM2) + off), fm);
            __stcg((float4*)(STQ(q, SPK2) + off), fs);
            __stcg((float4*)(STQ(q, BB2) + off), fb);
            wr_img(g_m2h[q], g_m2l[q], n, b, fm);
            wr_img(g_b2h[q], g_b2l[q], n, b, fb);
        }
        grid_bar(gen);

        // ---- P9: head (fused GEMM + blend + log-softmax), block = batch b ----
        {
            const int b = bid;
            float* srow = (float*)dsm;         // 1024
            float* red = srow + 1024;          // 160
            float* d3s = red + 160;            // 20
            float* m3s = d3s + 20;             // 20
            float* nms = m3s + 20;             // 20
            {
                float4 v = __ldcg((const float4*)(STQ(q, SPK2) + (size_t)b * H + tid * 4));
                *(float4*)(srow + tid * 4) = v;
            }
            __syncthreads();
            if (tid < 160) {
                const int o = tid >> 3, seg = tid & 7;
                const float* wr = w3x + (size_t)o * H + seg * 128;
                const float* ar = srow + seg * 128;
                float a = 0.f;
                #pragma unroll 4
                for (int k = 0; k < 128; k++) a += ar[k] * wr[k];
                red[tid] = a;
            }
            __syncthreads();
            if (tid < 20) {
                float s = 0.f;
                #pragma unroll
                for (int j = 0; j < 8; j++) s += red[tid * 8 + j];
                d3s[tid] = SCALE * (s + b3x[tid]);
                m3s[tid] = __ldcg(g_m3 + (size_t)p * B * O + b * O + tid);
            }
            __syncthreads();
            if (tid < 20) {
                const float* w = w3m + tid * (2 * O);
                float acc = b3m[tid];
                #pragma unroll
                for (int k = 0; k < O; k++) acc += d3s[k] * w[k] + m3s[k] * w[O + k];
                float tmv = sigmf(acc);
                float v = (1.0f - tmv) * m3s[tid] + d3s[tid] * tmv;
                nms[tid] = v;
                __stcg(g_m3 + (size_t)q * B * O + b * O + tid, v);
            }
            __syncthreads();
            if (tid == 0) {
                float mx = nms[0];
                #pragma unroll
                for (int o = 1; o < O; o++) mx = fmaxf(mx, nms[o]);
                float s = 0.f;
                #pragma unroll
                for (int o = 0; o < O; o++) s += expf(nms[o] - mx);
                float lse = logf(s) + mx;
                #pragma unroll
                for (int o = 0; o < O; o++)
                    out[(size_t)t * B * O + b * O + o] = nms[o] - lse;
            }
            __syncthreads();
        }
        // no barrier: next P1 depends only on P4 data (already barriered)
    }
    #undef STQ
}

// ---------------------------------------------------------------------------
// pre/post kernels
// ---------------------------------------------------------------------------
__global__ void init_bar_k() { if (threadIdx.x == 0) { g_arrive = 0u; g_phasec = 0u; } }

// x -> fp16 hi/lo tiles [t][chunk][b][64]
__global__ void pack_x_k(const float* __restrict__ in) {
    const int c = blockIdx.x, t = blockIdx.y;
    const int r = threadIdx.x >> 1, hf = (threadIdx.x & 1) * 32;
    const int k0 = c * 64 + hf;
    const float* sp = in + (size_t)r * T * DIN + (size_t)t * DIN + k0;
    size_t doff = ((size_t)t * 11 + c) * TILE + r * 64 + hf;
    #pragma unroll 8
    for (int i = 0; i < 32; i++) {
        float v = (k0 + i < DIN) ? sp[i] : 0.0f;
        __half hi = __float2half_rn(v);
        g_xh[doff + i] = hi;
        g_xl[doff + i] = __float2half_rn(v - __half2float(hi));
    }
}

// weights -> chunk-tile lists; writes hi to dh1 (and dh2 if set), lo to dl
__global__ void pack_w_k(const float* __restrict__ src, int Ksrc, int kbase,
                         __half* dh1, __half* dh2, __half* dl) {
    const int c = blockIdx.x, mt = blockIdx.y;
    const int r = threadIdx.x >> 1, hf = (threadIdx.x & 1) * 32;
    const int k0 = kbase + c * 64 + hf;
    const float* sp = src + (size_t)(mt * 128 + r) * Ksrc + k0;
    size_t doff = ((size_t)c * 8 + mt) * TILE + r * 64 + hf;
    #pragma unroll 8
    for (int i = 0; i < 32; i++) {
        float v = (k0 + i < Ksrc) ? sp[i] : 0.0f;
        __half hi = __float2half_rn(v);
        dh1[doff + i] = hi;
        if (dh2) dh2[doff + i] = hi;
        if (dl) dl[doff + i] = __float2half_rn(v - __half2float(hi));
    }
}

// initial states (batch-major copies + images, parity 0)
__global__ void init_state_k(const float* h0, const float* h1, const float* h2,
                             const float* h3, const float* h4, const float* h5,
                             const float* h6) {
    const int idx = blockIdx.x * 256 + threadIdx.x;
    const size_t off = (size_t)idx * 4;
    const int b = (int)(off >> 10), n = (int)(off & 1023);
    const float* hs[6] = { h0, h1, h2, h3, h4, h5 };
    for (int s = 0; s < 6; s++) {
        float4 v = *(const float4*)(hs[s] + off);
        *(float4*)(g_st + (size_t)s * BH + off) = v;
        if (s == MEM1) wr_img(g_m1h[0], g_m1l[0], n, b, v);
        else if (s == SPK1) wr_img(g_spk1i[0], 0, n, b, v);
        else if (s == BB1) wr_img(g_b1h[0], g_b1l[0], n, b, v);
        else if (s == MEM2) wr_img(g_m2h[0], g_m2l[0], n, b, v);
        else if (s == BB2) wr_img(g_b2h[0], g_b2l[0], n, b, v);
    }
    if (idx < B * O / 4)
        *(float4*)(g_m3 + off) = *(const float4*)(h6 + off);
}

// final: states parity 0 + m3 -> out tail
__global__ void copy_out_k(float* __restrict__ tail) {
    const size_t total = 6 * BH + B * O;
    const size_t off = ((size_t)blockIdx.x * 256 + threadIdx.x) * 4;
    if (off >= total) return;
    float4 v;
    if (off < 6 * BH) v = *(const float4*)(g_st + off);
    else              v = *(const float4*)(g_m3 + (off - 6 * BH));
    *(float4*)(tail + off) = v;
}

// ---------------------------------------------------------------------------
extern "C" void kernel_launch(void* const* d_in, const int* in_sizes, int n_in,
                              void* d_out, int out_size)
{
    (void)in_sizes; (void)n_in; (void)out_size;
    const float* inputs = (const float*)d_in[0];
    const float* h[7];
    for (int i = 0; i < 7; i++) h[i] = (const float*)d_in[1 + i];
    const float* w1x = (const float*)d_in[8];  const float* b1x = (const float*)d_in[9];
    const float* w1r = (const float*)d_in[10]; const float* b1r = (const float*)d_in[11];
    const float* w1m = (const float*)d_in[12]; const float* b1m = (const float*)d_in[13];
    const float* w1a = (const float*)d_in[14]; const float* b1a = (const float*)d_in[15];
    const float* w2x = (const float*)d_in[16]; const float* b2x = (const float*)d_in[17];
    const float* w2r = (const float*)d_in[18]; const float* b2r = (const float*)d_in[19];
    const float* w2m = (const float*)d_in[20]; const float* b2m = (const float*)d_in[21];
    const float* w2a = (const float*)d_in[22]; const float* b2a = (const float*)d_in[23];
    const float* w3x = (const float*)d_in[24]; const float* b3x = (const float*)d_in[25];
    const float* w3m = (const float*)d_in[26]; const float* b3m = (const float*)d_in[27];
    float* out = (float*)d_out;

    __half *WD1, *WD2, *WT1M, *WT1A, *WT2M, *WT2A;
    cudaGetSymbolAddress((void**)&WD1, g_wd1);
    cudaGetSymbolAddress((void**)&WD2, g_wd2);
    cudaGetSymbolAddress((void**)&WT1M, g_wt1m);
    cudaGetSymbolAddress((void**)&WT1A, g_wt1a);
    cudaGetSymbolAddress((void**)&WT2M, g_wt2m);
    cudaGetSymbolAddress((void**)&WT2A, g_wt2a);

    cudaFuncSetAttribute(snn_persist_k, cudaFuncAttributeMaxDynamicSharedMemorySize, 65536);

    // pack x and weights
    pack_x_k<<<dim3(11, T), 256>>>(inputs);
    pack_w_k<<<dim3(11, 8), 256>>>(w1x, DIN, 0, WD1, WD1 + (size_t)11 * T8, WD1 + (size_t)22 * T8);
    pack_w_k<<<dim3(16, 8), 256>>>(w1r, H, 0, WD1 + (size_t)33 * T8, 0, WD1 + (size_t)49 * T8);
    pack_w_k<<<dim3(16, 8), 256>>>(w2x, H, 0, WD2, 0, WD2 + (size_t)16 * T8);
    pack_w_k<<<dim3(16, 8), 256>>>(w2r, H, 0, WD2 + (size_t)32 * T8, 0, WD2 + (size_t)48 * T8);
    pack_w_k<<<dim3(16, 8), 256>>>(w1m, 2 * H, 0,    WT1M, WT1M + (size_t)16 * T8, WT1M + (size_t)32 * T8);
    pack_w_k<<<dim3(16, 8), 256>>>(w1m, 2 * H, 1024, WT1M + (size_t)48 * T8, WT1M + (size_t)64 * T8, WT1M + (size_t)80 * T8);
    pack_w_k<<<dim3(16, 8), 256>>>(w1a, 2 * H, 0,    WT1A, WT1A + (size_t)16 * T8, WT1A + (size_t)32 * T8);
    pack_w_k<<<dim3(16, 8), 256>>>(w1a, 2 * H, 1024, WT1A + (size_t)48 * T8, WT1A + (size_t)64 * T8, WT1A + (size_t)80 * T8);
    pack_w_k<<<dim3(16, 8), 256>>>(w2m, 2 * H, 0,    WT2M, WT2M + (size_t)16 * T8, WT2M + (size_t)32 * T8);
    pack_w_k<<<dim3(16, 8), 256>>>(w2m, 2 * H, 1024, WT2M + (size_t)48 * T8, WT2M + (size_t)64 * T8, WT2M + (size_t)80 * T8);
    pack_w_k<<<dim3(16, 8), 256>>>(w2a, 2 * H, 0,    WT2A, WT2A + (size_t)16 * T8, WT2A + (size_t)32 * T8);
    pack_w_k<<<dim3(16, 8), 256>>>(w2a, 2 * H, 1024, WT2A + (size_t)48 * T8, WT2A + (size_t)64 * T8, WT2A + (size_t)80 * T8);

    init_state_k<<<128, 256>>>(h[0], h[1], h[2], h[3], h[4], h[5], h[6]);
    init_bar_k<<<1, 32>>>();

    snn_persist_k<<<NBLK, 256, 65536>>>(b1x, b1r, b1m, b1a, b2x, b2r, b2m, b2a,
                                        w3x, b3x, w3m, b3m, out);

    copy_out_k<<<(6 * BH + B * O + 1023) / 1024, 256>>>(out + (size_t)T * B * O);
}

// round 13
// speedup vs baseline: 1.6919x; 1.0480x over previous
#include <cuda_runtime.h>
#include <cuda_fp16.h>
#include <cstddef>

// ===========================================================================
// SNN forward: persistent kernel; warp-level mma.sync.m16n8k16 (HMMA) with
// fp16 hi/lo splitting. Batch-major everywhere. fp16 operand tiles stored in
// global as linear [chunk][row(128)][64 halves]; blocks cp.async them into
// SW128-swizzled smem; A(M)=activation(batch), B(N)=weights(neuron).
// R13: R12 structure (fused head, 7 barriers/step, pack consolidation) with
// nanosleep(32) backoff restored in the grid barrier (de-risk container).
// ===========================================================================

#define B     128
#define T     100
#define DIN   700
#define H     1024
#define O     20
#define NBLK  128
#define SCALE 0.09999950000374997f   // 0.1/sqrt(1+1e-5)
#define TILE  8192                   // halves per 128x64 tile
#define T8    (8 * TILE)             // halves per chunk across 8 mtiles
#define BH    (B * H)

enum { MEM1 = 0, SPK1, BB1, MEM2, SPK2, BB2 };

// ---- fp16 images ----
__device__ __half g_xh[(size_t)T * 11 * TILE], g_xl[(size_t)T * 11 * TILE];
__device__ __half g_wd1[(size_t)65 * T8], g_wd2[(size_t)64 * T8];
__device__ __half g_wt1m[(size_t)96 * T8], g_wt1a[(size_t)96 * T8];
__device__ __half g_wt2m[(size_t)96 * T8], g_wt2a[(size_t)96 * T8];
__device__ __half g_spk1i[2][16 * TILE];
__device__ __half g_m1h[2][16 * TILE], g_m1l[2][16 * TILE];
__device__ __half g_b1h[2][16 * TILE], g_b1l[2][16 * TILE];
__device__ __half g_m2h[2][16 * TILE], g_m2l[2][16 * TILE];
__device__ __half g_b2h[2][16 * TILE], g_b2l[2][16 * TILE];
__device__ __half g_d1h[16 * TILE], g_d1l[16 * TILE];
__device__ __half g_d2h[16 * TILE], g_d2l[16 * TILE];
// ---- fp32 state/scratch (batch-major [b][n]) ----
__device__ float g_st[12 * BH];              // [parity][6][BH]
__device__ float g_m3[2 * B * O];
__device__ float g_d1[BH], g_d2[BH];
__device__ float g_part[16 * BH];
__device__ float g_pma[16 * BH];             // [z*8+s][BH]
__device__ unsigned g_arrive, g_phasec;

// ---------------------------------------------------------------------------
__device__ __forceinline__ float sigmf(float x) { return 1.0f / (1.0f + expf(-x)); }
#define SW128(o) ((o) ^ (((o) >> 3) & 0x70))

__device__ __forceinline__ void cpa16(void* dst_smem, const void* src) {
    unsigned d = (unsigned)__cvta_generic_to_shared(dst_smem);
    asm volatile("cp.async.cg.shared.global [%0], [%1], 16;\n" :: "r"(d), "l"(src));
}
__device__ __forceinline__ void cpa_commit() {
    asm volatile("cp.async.commit_group;\n" ::: "memory");
}
__device__ __forceinline__ void cpa_wait0() {
    asm volatile("cp.async.wait_group 0;\n" ::: "memory");
}
__device__ __forceinline__ unsigned smem_u32(const void* p) {
    return (unsigned)__cvta_generic_to_shared(p);
}
__device__ __forceinline__ void ldsm4(unsigned* r, unsigned addr) {
    asm volatile("ldmatrix.sync.aligned.m8n8.x4.shared.b16 {%0,%1,%2,%3}, [%4];"
        : "=r"(r[0]), "=r"(r[1]), "=r"(r[2]), "=r"(r[3]) : "r"(addr));
}
__device__ __forceinline__ void mma16816(float* d, const unsigned* a,
                                         unsigned b0, unsigned b1) {
    asm volatile(
        "mma.sync.aligned.m16n8k16.row.col.f32.f16.f16.f32 "
        "{%0,%1,%2,%3}, {%4,%5,%6,%7}, {%8,%9}, {%0,%1,%2,%3};"
        : "+f"(d[0]), "+f"(d[1]), "+f"(d[2]), "+f"(d[3])
        : "r"(a[0]), "r"(a[1]), "r"(a[2]), "r"(a[3]), "r"(b0), "r"(b1));
}

// sense barrier with light nanosleep backoff
__device__ __forceinline__ void grid_bar(unsigned& gen) {
    __syncthreads();
    if (threadIdx.x == 0) {
        __threadfence();
        unsigned t = atomicAdd(&g_arrive, 1u);
        if (t == NBLK - 1) {
            *(volatile unsigned*)&g_arrive = 0u;
            __threadfence();
            atomicAdd(&g_phasec, 1u);
        } else {
            volatile unsigned* ph = &g_phasec;
            while (*ph == gen) { __nanosleep(32); }
            __threadfence();
        }
    }
    __syncthreads();
    gen++;
}

__device__ __forceinline__ unsigned packh(__half a, __half b) {
    __half2 t = __halves2half2(a, b);
    return *(unsigned*)&t;
}
// write fp16 images (hi, optional lo) for 4 consecutive n at (b, n)
__device__ __forceinline__ void wr_img(__half* hi, __half* lo, int n, int b, float4 v) {
    int ii = (n >> 6) * TILE + b * 64 + (n & 63);
    __half h0 = __float2half_rn(v.x), h1 = __float2half_rn(v.y);
    __half h2 = __float2half_rn(v.z), h3 = __float2half_rn(v.w);
    __stcg((uint2*)(hi + ii), make_uint2(packh(h0, h1), packh(h2, h3)));
    if (lo) {
        __half l0 = __float2half_rn(v.x - __half2float(h0));
        __half l1 = __float2half_rn(v.y - __half2float(h1));
        __half l2 = __float2half_rn(v.z - __half2float(h2));
        __half l3 = __float2half_rn(v.w - __half2float(h3));
        __stcg((uint2*)(lo + ii), make_uint2(packh(l0, l1), packh(l2, l3)));
    }
}

// ---------------------------------------------------------------------------
// A-operand (activation) tile resolver. stage: 0=dense1, 1=dense2, 2=tau1, 3=tau2
// ---------------------------------------------------------------------------
__device__ __forceinline__ const __half* resolve_A(int stage, int z, int c, int t, int p) {
    if (stage == 0) {
        if (c < 33) {
            int idx = (c < 11) ? c : (c < 22 ? c - 11 : c - 22);
            const __half* base = (c >= 11 && c < 22) ? g_xl : g_xh;
            return base + ((size_t)t * 11 + idx) * TILE;
        }
        return g_spk1i[p] + (size_t)((c - 33) & 15) * TILE;
    }
    if (stage == 1) {
        int sub = c >> 4, cc = c & 15;
        return g_spk1i[sub < 2 ? (p ^ 1) : p] + (size_t)cc * TILE;
    }
    int sub = c >> 4, cc = c & 15, l = stage - 2;
    const __half* base;
    if (sub < 3) {
        base = (sub == 1) ? (l ? g_d2l : g_d1l) : (l ? g_d2h : g_d1h);
    } else {
        int s2 = sub - 3;
        if (!z) base = (s2 == 1) ? (l ? g_m2l[p] : g_m1l[p]) : (l ? g_m2h[p] : g_m1h[p]);
        else    base = (s2 == 1) ? (l ? g_b2l[p] : g_b1l[p]) : (l ? g_b2h[p] : g_b1h[p]);
    }
    return base + (size_t)cc * TILE;
}

// ---------------------------------------------------------------------------
// GEMM job via mma.sync: chunks [tb,te) -> partial[b][mt*128..+128].
// dsm: 2 x 32KB buffers (A act tile 16KB + W tile 16KB each).
// Warp grid: 4 m-quadrants (batch, 32 rows) x 2 n-halves (neuron, 64 cols).
// ---------------------------------------------------------------------------
__device__ void mma_run(const __half* Wimg, int stage, int z, int t, int p, int mt,
                        int tb, int te, float* __restrict__ partial, char* dsm)
{
    const int tid = threadIdx.x;
    const int warp = tid >> 5, lane = tid & 31;
    const int wm = warp >> 1;    // batch quadrant
    const int wn = warp & 1;     // neuron half
    const int nb = te - tb;

    float acc[16][4];
    #pragma unroll
    for (int i = 0; i < 16; i++)
        acc[i][0] = acc[i][1] = acc[i][2] = acc[i][3] = 0.f;

    auto load_tile = [&](int c, int buf) {
        const char* ap = (const char*)resolve_A(stage, z, c, t, p);
        const char* wp = (const char*)(Wimg + ((size_t)c * 8 + mt) * TILE);
        char* ad = dsm + buf * 32768;
        char* wd = ad + 16384;
        #pragma unroll
        for (int i = 0; i < 4; i++) {
            int off = (tid + i * 256) * 16;
            int sw = SW128(off);
            cpa16(ad + sw, ap + off);
            cpa16(wd + sw, wp + off);
        }
        cpa_commit();
    };

    load_tile(tb, 0);
    for (int i = 0; i < nb; i++) {
        cpa_wait0();
        __syncthreads();                 // buffer i ready; compute i-1 done
        if (i + 1 < nb) load_tile(tb + i + 1, (i + 1) & 1);   // overlaps compute
        const char* ad = dsm + (i & 1) * 32768;
        const char* wd = ad + 16384;
        const unsigned ab = smem_u32(ad), wb = smem_u32(wd);

        #pragma unroll
        for (int ks = 0; ks < 4; ks++) {
            unsigned a0[4], a1[4];
            {
                int row = wm * 32 + (lane & 7) + ((lane >> 3) & 1) * 8;
                int kb = ks * 32 + (lane >> 4) * 16;
                ldsm4(a0, ab + SW128(row * 128 + kb));
                ldsm4(a1, ab + SW128((row + 16) * 128 + kb));
            }
            unsigned bf[4][4];
            #pragma unroll
            for (int nf = 0; nf < 4; nf++) {
                int nr = wn * 64 + nf * 16 + (lane & 7) + ((lane >> 4) & 1) * 8;
                int kb = ks * 32 + ((lane >> 3) & 1) * 16;
                ldsm4(bf[nf], wb + SW128(nr * 128 + kb));
            }
            #pragma unroll
            for (int nf = 0; nf < 4; nf++) {
                mma16816(acc[nf * 2 + 0],     a0, bf[nf][0], bf[nf][1]);
                mma16816(acc[nf * 2 + 1],     a0, bf[nf][2], bf[nf][3]);
                mma16816(acc[8 + nf * 2 + 0], a1, bf[nf][0], bf[nf][1]);
                mma16816(acc[8 + nf * 2 + 1], a1, bf[nf][2], bf[nf][3]);
            }
        }
    }
    __syncthreads();

    // epilogue: acc -> partial[b][mt*128 + n]
    const int ncol0 = mt * 128 + wn * 64 + (lane & 3) * 2;
    #pragma unroll
    for (int mf = 0; mf < 2; mf++) {
        const int row0 = wm * 32 + mf * 16 + (lane >> 2);
        #pragma unroll
        for (int n8 = 0; n8 < 8; n8++) {
            float* p0 = partial + (size_t)row0 * H + ncol0 + n8 * 8;
            float* p1 = partial + (size_t)(row0 + 8) * H + ncol0 + n8 * 8;
            __stcg((float2*)p0, make_float2(acc[mf * 8 + n8][0], acc[mf * 8 + n8][1]));
            __stcg((float2*)p1, make_float2(acc[mf * 8 + n8][2], acc[mf * 8 + n8][3]));
        }
    }
}

// ---------------------------------------------------------------------------
// persistent kernel
// ---------------------------------------------------------------------------
__global__ void __launch_bounds__(256) snn_persist_k(
    const float* __restrict__ b1x, const float* __restrict__ b1r,
    const float* __restrict__ b1m, const float* __restrict__ b1a,
    const float* __restrict__ b2x, const float* __restrict__ b2r,
    const float* __restrict__ b2m, const float* __restrict__ b2a,
    const float* __restrict__ w3x, const float* __restrict__ b3x,
    const float* __restrict__ w3m, const float* __restrict__ b3m,
    float* __restrict__ out)
{
    extern __shared__ __align__(1024) char dsm[];   // 64 KB dynamic

    const int bid = blockIdx.x, tid = threadIdx.x;
    unsigned gen = 0;

    #define STQ(pp, ss) (g_st + ((size_t)(pp) * 6 + (ss)) * BH)

    for (int t = 0; t < T; t++) {
        const int p = t & 1, q = p ^ 1;

        // ---- P1: dense1 MMA (65 chunks; 8 mt x 16 splits) ----
        {
            const int mt = bid & 7, s = bid >> 3;
            mma_run(g_wd1, 0, 0, t, p, mt, (65 * s) / 16, (65 * (s + 1)) / 16,
                    g_part + (size_t)s * BH, dsm);
        }
        grid_bar(gen);

        // ---- P2: reduce D1 (16 slices) + D1 images ----
        {
            const size_t off = ((size_t)bid * 256 + tid) * 4;
            float4 s4 = make_float4(0.f, 0.f, 0.f, 0.f);
            #pragma unroll
            for (int k = 0; k < 16; k++) {
                float4 pp = __ldcg((const float4*)(g_part + (size_t)k * BH + off));
                s4.x += pp.x; s4.y += pp.y; s4.z += pp.z; s4.w += pp.w;
            }
            const int b = (int)(off >> 10), n = (int)(off & 1023);
            float4 bx = *(const float4*)(b1x + n), br = *(const float4*)(b1r + n);
            float4 r = make_float4(SCALE * (s4.x + bx.x + br.x), SCALE * (s4.y + bx.y + br.y),
                                   SCALE * (s4.z + bx.z + br.z), SCALE * (s4.w + bx.w + br.w));
            __stcg((float4*)(g_d1 + off), r);
            wr_img(g_d1h, g_d1l, n, b, r);
        }
        grid_bar(gen);

        // ---- P3: tau1 MMA (96 chunks per z; 8mt x 8s x 2z) ----
        {
            const int mt = bid & 7, s = (bid >> 3) & 7, z = bid >> 6;
            mma_run(z ? g_wt1a : g_wt1m, 2, z, t, p, mt, s * 12, s * 12 + 12,
                    g_pma + (size_t)(z * 8 + s) * BH, dsm);
        }
        grid_bar(gen);

        // ---- P4: tau1 reduce + adaptive update -> parity q (+ images[q]) ----
        {
            const size_t off = ((size_t)bid * 256 + tid) * 4;
            float4 sm = make_float4(0.f, 0.f, 0.f, 0.f), sa = sm;
            #pragma unroll
            for (int k = 0; k < 8; k++) {
                float4 pm = __ldcg((const float4*)(g_pma + (size_t)k * BH + off));
                float4 pa = __ldcg((const float4*)(g_pma + (size_t)(8 + k) * BH + off));
                sm.x += pm.x; sm.y += pm.y; sm.z += pm.z; sm.w += pm.w;
                sa.x += pa.x; sa.y += pa.y; sa.z += pa.z; sa.w += pa.w;
            }
            const int b = (int)(off >> 10), n = (int)(off & 1023);
            float4 bm4 = *(const float4*)(b1m + n), ba4 = *(const float4*)(b1a + n);
            float4 dn = __ldcg((const float4*)(g_d1 + off));
            float4 me = __ldcg((const float4*)(STQ(p, MEM1) + off));
            float4 bo = __ldcg((const float4*)(STQ(p, BB1) + off));
            float4 sp = __ldcg((const float4*)(STQ(p, SPK1) + off));
            float tm[4] = { sigmf(sm.x + bm4.x), sigmf(sm.y + bm4.y),
                            sigmf(sm.z + bm4.z), sigmf(sm.w + bm4.w) };
            float ta[4] = { sigmf(sa.x + ba4.x), sigmf(sa.y + ba4.y),
                            sigmf(sa.z + ba4.z), sigmf(sa.w + ba4.w) };
            float dv[4] = { dn.x, dn.y, dn.z, dn.w }, mv[4] = { me.x, me.y, me.z, me.w };
            float bv[4] = { bo.x, bo.y, bo.z, bo.w }, sv[4] = { sp.x, sp.y, sp.z, sp.w };
            float nm[4], ns[4], nb[4];
            #pragma unroll
            for (int j = 0; j < 4; j++) {
                float bn = ta[j] * bv[j] + (1.0f - ta[j]) * sv[j];
                float mn = mv[j] + (dv[j] - mv[j]) * tm[j];
                float s = (mn - (0.1f + 1.8f * bn)) > 0.0f ? 1.0f : 0.0f;
                nm[j] = (1.0f - s) * mn; ns[j] = s; nb[j] = bn;
            }
            float4 fm = make_float4(nm[0], nm[1], nm[2], nm[3]);
            float4 fs = make_float4(ns[0], ns[1], ns[2], ns[3]);
            float4 fb = make_float4(nb[0], nb[1], nb[2], nb[3]);
            __stcg((float4*)(STQ(q, MEM1) + off), fm);
            __stcg((float4*)(STQ(q, SPK1) + off), fs);
            __stcg((float4*)(STQ(q, BB1) + off), fb);
            wr_img(g_m1h[q], g_m1l[q], n, b, fm);
            wr_img(g_spk1i[q], 0, n, b, fs);
            wr_img(g_b1h[q], g_b1l[q], n, b, fb);
        }
        grid_bar(gen);

        // ---- P5: dense2 MMA (64 chunks; 8 mt x 16 splits) ----
        {
            const int mt = bid & 7, s = bid >> 3;
            mma_run(g_wd2, 1, 0, t, p, mt, s * 4, s * 4 + 4,
                    g_part + (size_t)s * BH, dsm);
        }
        grid_bar(gen);

        // ---- P6: reduce D2 + images ----
        {
            const size_t off = ((size_t)bid * 256 + tid) * 4;
            float4 s4 = make_float4(0.f, 0.f, 0.f, 0.f);
            #pragma unroll
            for (int k = 0; k < 16; k++) {
                float4 pp = __ldcg((const float4*)(g_part + (size_t)k * BH + off));
                s4.x += pp.x; s4.y += pp.y; s4.z += pp.z; s4.w += pp.w;
            }
            const int b = (int)(off >> 10), n = (int)(off & 1023);
            float4 bx = *(const float4*)(b2x + n), br = *(const float4*)(b2r + n);
            float4 r = make_float4(SCALE * (s4.x + bx.x + br.x), SCALE * (s4.y + bx.y + br.y),
                                   SCALE * (s4.z + bx.z + br.z), SCALE * (s4.w + bx.w + br.w));
            __stcg((float4*)(g_d2 + off), r);
            wr_img(g_d2h, g_d2l, n, b, r);
        }
        grid_bar(gen);

        // ---- P7: tau2 MMA ----
        {
            const int mt = bid & 7, s = (bid >> 3) & 7, z = bid >> 6;
            mma_run(z ? g_wt2a : g_wt2m, 3, z, t, p, mt, s * 12, s * 12 + 12,
                    g_pma + (size_t)(z * 8 + s) * BH, dsm);
        }
        grid_bar(gen);

        // ---- P8: tau2 reduce + update -> parity q, FUSED head (block = batch b) ----
        {
            const int b = bid;
            const size_t off = ((size_t)bid * 256 + tid) * 4;  // b = bid, n = tid*4
            float4 sm = make_float4(0.f, 0.f, 0.f, 0.f), sa = sm;
            #pragma unroll
            for (int k = 0; k < 8; k++) {
                float4 pm = __ldcg((const float4*)(g_pma + (size_t)k * BH + off));
                float4 pa = __ldcg((const float4*)(g_pma + (size_t)(8 + k) * BH + off));
                sm.x += pm.x; sm.y += pm.y; sm.z += pm.z; sm.w += pm.w;
                sa.x += pa.x; sa.y += pa.y; sa.z += pa.z; sa.w += pa.w;
            }
            const int n = (int)(off & 1023);
            float4 bm4 = *(const float4*)(b2m + n), ba4 = *(const float4*)(b2a + n);
            float4 dn = __ldcg((const float4*)(g_d2 + off));
            float4 me = __ldcg((const float4*)(STQ(p, MEM2) + off));
            float4 bo = __ldcg((const float4*)(STQ(p, BB2) + off));
            float4 sp = __ldcg((const float4*)(STQ(p, SPK2) + off));
            float tm[4] = { sigmf(sm.x + bm4.x), sigmf(sm.y + bm4.y),
                            sigmf(sm.z + bm4.z), sigmf(sm.w + bm4.w) };
            float ta[4] = { sigmf(sa.x + ba4.x), sigmf(sa.y + ba4.y),
                            sigmf(sa.z + ba4.z), sigmf(sa.w + ba4.w) };
            float dv[4] = { dn.x, dn.y, dn.z, dn.w }, mv[4] = { me.x, me.y, me.z, me.w };
            float bv[4] = { bo.x, bo.y, bo.z, bo.w }, sv[4] = { sp.x, sp.y, sp.z, sp.w };
            float nm[4], ns[4], nb[4];
            #pragma unroll
            for (int j = 0; j < 4; j++) {
                float bn = ta[j] * bv[j] + (1.0f - ta[j]) * sv[j];
                float mn = mv[j] + (dv[j] - mv[j]) * tm[j];
                float s = (mn - (0.1f + 1.8f * bn)) > 0.0f ? 1.0f : 0.0f;
                nm[j] = (1.0f - s) * mn; ns[j] = s; nb[j] = bn;
            }
            float4 fm = make_float4(nm[0], nm[1], nm[2], nm[3]);
            float4 fs = make_float4(ns[0], ns[1], ns[2], ns[3]);
            float4 fb = make_float4(nb[0], nb[1], nb[2], nb[3]);
            __stcg((float4*)(STQ(q, MEM2) + off), fm);
            __stcg((float4*)(STQ(q, SPK2) + off), fs);
            __stcg((float4*)(STQ(q, BB2) + off), fb);
            wr_img(g_m2h[q], g_m2l[q], n, b, fm);
            wr_img(g_b2h[q], g_b2l[q], n, b, fb);

            // -- fused head: this block owns the full spk2 row of batch b --
            float* srow = (float*)dsm;         // 1024
            float* red = srow + 1024;          // 160
            float* d3s = red + 160;            // 20
            float* m3s = d3s + 20;             // 20
            float* nms = m3s + 20;             // 20
            *(float4*)(srow + tid * 4) = fs;
            __syncthreads();
            if (tid < 160) {
                const int o = tid >> 3, seg = tid & 7;
                const float* wr = w3x + (size_t)o * H + seg * 128;
                const float* ar = srow + seg * 128;
                float a = 0.f;
                #pragma unroll 4
                for (int k = 0; k < 128; k++) a += ar[k] * wr[k];
                red[tid] = a;
            }
            __syncthreads();
            if (tid < 20) {
                float s = 0.f;
                #pragma unroll
                for (int j = 0; j < 8; j++) s += red[tid * 8 + j];
                d3s[tid] = SCALE * (s + b3x[tid]);
                m3s[tid] = __ldcg(g_m3 + (size_t)p * B * O + b * O + tid);
            }
            __syncthreads();
            if (tid < 20) {
                const float* w = w3m + tid * (2 * O);
                float acc = b3m[tid];
                #pragma unroll
                for (int k = 0; k < O; k++) acc += d3s[k] * w[k] + m3s[k] * w[O + k];
                float tmv = sigmf(acc);
                float v = (1.0f - tmv) * m3s[tid] + d3s[tid] * tmv;
                nms[tid] = v;
                __stcg(g_m3 + (size_t)q * B * O + b * O + tid, v);
            }
            __syncthreads();
            if (tid == 0) {
                float mx = nms[0];
                #pragma unroll
                for (int o = 1; o < O; o++) mx = fmaxf(mx, nms[o]);
                float s = 0.f;
                #pragma unroll
                for (int o = 0; o < O; o++) s += expf(nms[o] - mx);
                float lse = logf(s) + mx;
                #pragma unroll
                for (int o = 0; o < O; o++)
                    out[(size_t)t * B * O + b * O + o] = nms[o] - lse;
            }
            __syncthreads();
        }
        // no trailing barrier: next P1 touches only P4-barriered data + g_part,
        // which no P8 straggler reads; bar-after-next-P1 orders g_pma reuse.
    }
    #undef STQ
}

// ---------------------------------------------------------------------------
// pre/post kernels
// ---------------------------------------------------------------------------
__global__ void init_bar_k() { if (threadIdx.x == 0) { g_arrive = 0u; g_phasec = 0u; } }
__global__ void noop_k() {}

// x -> fp16 hi/lo tiles [t][chunk][b][64]
__global__ void pack_x_k(const float* __restrict__ in) {
    const int c = blockIdx.x, t = blockIdx.y;
    const int r = threadIdx.x >> 1, hf = (threadIdx.x & 1) * 32;
    const int k0 = c * 64 + hf;
    const float* sp = in + (size_t)r * T * DIN + (size_t)t * DIN + k0;
    size_t doff = ((size_t)t * 11 + c) * TILE + r * 64 + hf;
    #pragma unroll 8
    for (int i = 0; i < 32; i++) {
        float v = (k0 + i < DIN) ? sp[i] : 0.0f;
        __half hi = __float2half_rn(v);
        g_xh[doff + i] = hi;
        g_xl[doff + i] = __float2half_rn(v - __half2float(hi));
    }
}

// all 12 weight-pack jobs in one launch: grid (16, 8, 12)
__global__ void pack_w_all_k(
    const float* __restrict__ w1x, const float* __restrict__ w1r,
    const float* __restrict__ w2x, const float* __restrict__ w2r,
    const float* __restrict__ w1m, const float* __restrict__ w1a,
    const float* __restrict__ w2m, const float* __restrict__ w2a)
{
    const int c = blockIdx.x, mt = blockIdx.y, job = blockIdx.z;
    const float* src; int Ksrc, kb, climit;
    __half *dh1, *dh2, *dl;
    switch (job) {
        case 0:  src = w1x; Ksrc = DIN;   kb = 0;    climit = 11;
                 dh1 = g_wd1;                 dh2 = g_wd1 + (size_t)11 * T8; dl = g_wd1 + (size_t)22 * T8; break;
        case 1:  src = w1r; Ksrc = H;     kb = 0;    climit = 16;
                 dh1 = g_wd1 + (size_t)33 * T8; dh2 = 0; dl = g_wd1 + (size_t)49 * T8; break;
        case 2:  src = w2x; Ksrc = H;     kb = 0;    climit = 16;
                 dh1 = g_wd2;                 dh2 = 0; dl = g_wd2 + (size_t)16 * T8; break;
        case 3:  src = w2r; Ksrc = H;     kb = 0;    climit = 16;
                 dh1 = g_wd2 + (size_t)32 * T8; dh2 = 0; dl = g_wd2 + (size_t)48 * T8; break;
        case 4:  src = w1m; Ksrc = 2 * H; kb = 0;    climit = 16;
                 dh1 = g_wt1m;                dh2 = g_wt1m + (size_t)16 * T8; dl = g_wt1m + (size_t)32 * T8; break;
        case 5:  src = w1m; Ksrc = 2 * H; kb = 1024; climit = 16;
                 dh1 = g_wt1m + (size_t)48 * T8; dh2 = g_wt1m + (size_t)64 * T8; dl = g_wt1m + (size_t)80 * T8; break;
        case 6:  src = w1a; Ksrc = 2 * H; kb = 0;    climit = 16;
                 dh1 = g_wt1a;                dh2 = g_wt1a + (size_t)16 * T8; dl = g_wt1a + (size_t)32 * T8; break;
        case 7:  src = w1a; Ksrc = 2 * H; kb = 1024; climit = 16;
                 dh1 = g_wt1a + (size_t)48 * T8; dh2 = g_wt1a + (size_t)64 * T8; dl = g_wt1a + (size_t)80 * T8; break;
        case 8:  src = w2m; Ksrc = 2 * H; kb = 0;    climit = 16;
                 dh1 = g_wt2m;                dh2 = g_wt2m + (size_t)16 * T8; dl = g_wt2m + (size_t)32 * T8; break;
        case 9:  src = w2m; Ksrc = 2 * H; kb = 1024; climit = 16;
                 dh1 = g_wt2m + (size_t)48 * T8; dh2 = g_wt2m + (size_t)64 * T8; dl = g_wt2m + (size_t)80 * T8; break;
        case 10: src = w2a; Ksrc = 2 * H; kb = 0;    climit = 16;
                 dh1 = g_wt2a;                dh2 = g_wt2a + (size_t)16 * T8; dl = g_wt2a + (size_t)32 * T8; break;
        default: src = w2a; Ksrc = 2 * H; kb = 1024; climit = 16;
                 dh1 = g_wt2a + (size_t)48 * T8; dh2 = g_wt2a + (size_t)64 * T8; dl = g_wt2a + (size_t)80 * T8; break;
    }
    if (c >= climit) return;
    const int r = threadIdx.x >> 1, hf = (threadIdx.x & 1) * 32;
    const int k0 = kb + c * 64 + hf;
    const float* sp = src + (size_t)(mt * 128 + r) * Ksrc + k0;
    size_t doff = ((size_t)c * 8 + mt) * TILE + r * 64 + hf;
    #pragma unroll 8
    for (int i = 0; i < 32; i++) {
        float v = (k0 + i < Ksrc) ? sp[i] : 0.0f;
        __half hi = __float2half_rn(v);
        dh1[doff + i] = hi;
        if (dh2) dh2[doff + i] = hi;
        if (dl) dl[doff + i] = __float2half_rn(v - __half2float(hi));
    }
}

// initial states (batch-major copies + images, parity 0)
__global__ void init_state_k(const float* h0, const float* h1, const float* h2,
                             const float* h3, const float* h4, const float* h5,
                             const float* h6) {
    const int idx = blockIdx.x * 256 + threadIdx.x;
    const size_t off = (size_t)idx * 4;
    const int b = (int)(off >> 10), n = (int)(off & 1023);
    const float* hs[6] = { h0, h1, h2, h3, h4, h5 };
    for (int s = 0; s < 6; s++) {
        float4 v = *(const float4*)(hs[s] + off);
        *(float4*)(g_st + (size_t)s * BH + off) = v;
        if (s == MEM1) wr_img(g_m1h[0], g_m1l[0], n, b, v);
        else if (s == SPK1) wr_img(g_spk1i[0], 0, n, b, v);
        else if (s == BB1) wr_img(g_b1h[0], g_b1l[0], n, b, v);
        else if (s == MEM2) wr_img(g_m2h[0], g_m2l[0], n, b, v);
        else if (s == BB2) wr_img(g_b2h[0], g_b2l[0], n, b, v);
    }
    if (idx < B * O / 4)
        *(float4*)(g_m3 + off) = *(const float4*)(h6 + off);
}

// final: states parity 0 + m3 -> out tail
__global__ void copy_out_k(float* __restrict__ tail) {
    const size_t total = 6 * BH + B * O;
    const size_t off = ((size_t)blockIdx.x * 256 + threadIdx.x) * 4;
    if (off >= total) return;
    float4 v;
    if (off < 6 * BH) v = *(const float4*)(g_st + off);
    else              v = *(const float4*)(g_m3 + (off - 6 * BH));
    *(float4*)(tail + off) = v;
}

// ---------------------------------------------------------------------------
extern "C" void kernel_launch(void* const* d_in, const int* in_sizes, int n_in,
                              void* d_out, int out_size)
{
    (void)in_sizes; (void)n_in; (void)out_size;
    const float* inputs = (const float*)d_in[0];
    const float* h[7];
    for (int i = 0; i < 7; i++) h[i] = (const float*)d_in[1 + i];
    const float* w1x = (const float*)d_in[8];  const float* b1x = (const float*)d_in[9];
    const float* w1r = (const float*)d_in[10]; const float* b1r = (const float*)d_in[11];
    const float* w1m = (const float*)d_in[12]; const float* b1m = (const float*)d_in[13];
    const float* w1a = (const float*)d_in[14]; const float* b1a = (const float*)d_in[15];
    const float* w2x = (const float*)d_in[16]; const float* b2x = (const float*)d_in[17];
    const float* w2r = (const float*)d_in[18]; const float* b2r = (const float*)d_in[19];
    const float* w2m = (const float*)d_in[20]; const float* b2m = (const float*)d_in[21];
    const float* w2a = (const float*)d_in[22]; const float* b2a = (const float*)d_in[23];
    const float* w3x = (const float*)d_in[24]; const float* b3x = (const float*)d_in[25];
    const float* w3m = (const float*)d_in[26]; const float* b3m = (const float*)d_in[27];
    float* out = (float*)d_out;

    cudaFuncSetAttribute(snn_persist_k, cudaFuncAttributeMaxDynamicSharedMemorySize, 65536);

    // launches 1..5, then snn_persist_k is launch #6 (ncu -s 5 -c 1 captures it)
    pack_x_k<<<dim3(11, T), 256>>>(inputs);
    pack_w_all_k<<<dim3(16, 8, 12), 256>>>(w1x, w1r, w2x, w2r, w1m, w1a, w2m, w2a);
    init_state_k<<<128, 256>>>(h[0], h[1], h[2], h[3], h[4], h[5], h[6]);
    init_bar_k<<<1, 32>>>();
    noop_k<<<1, 32>>>();

    snn_persist_k<<<NBLK, 256, 65536>>>(b1x, b1r, b1m, b1a, b2x, b2r, b2m, b2a,
                                        w3x, b3x, w3m, b3m, out);

    copy_out_k<<<(6 * BH + B * O + 1023) / 1024, 256>>>(out + (size_t)T * B * O);
}

// round 17
// speedup vs baseline: 1.6983x; 1.0038x over previous
#include <cuda_runtime.h>
#include <cuda_fp16.h>
#include <cstddef>

// ===========================================================================
// SNN forward: persistent kernel; warp-level mma.sync.m16n8k16 (HMMA) with
// fp16 hi/lo splitting. Batch-major everywhere. fp16 operand tiles stored in
// global as linear [chunk][row(128)][64 halves]; blocks cp.async them into
// SW128-swizzled smem; A(M)=activation(batch), B(N)=weights(neuron).
// R14: 144 persistent blocks (8mt x 18s dense, 8mt x 9s x 2z tau), hybrid
// spin barrier, persist as 4th launch (global #6 for ncu -s 5).
// ===========================================================================

#define B     128
#define T     100
#define DIN   700
#define H     1024
#define O     20
#define NBLK  144
#define SCALE 0.09999950000374997f   // 0.1/sqrt(1+1e-5)
#define TILE  8192                   // halves per 128x64 tile
#define T8    (8 * TILE)             // halves per chunk across 8 mtiles
#define BH    (B * H)

enum { MEM1 = 0, SPK1, BB1, MEM2, SPK2, BB2 };

// ---- fp16 images ----
__device__ __half g_xh[(size_t)T * 11 * TILE], g_xl[(size_t)T * 11 * TILE];
__device__ __half g_wd1[(size_t)65 * T8], g_wd2[(size_t)64 * T8];
__device__ __half g_wt1m[(size_t)96 * T8], g_wt1a[(size_t)96 * T8];
__device__ __half g_wt2m[(size_t)96 * T8], g_wt2a[(size_t)96 * T8];
__device__ __half g_spk1i[2][16 * TILE];
__device__ __half g_m1h[2][16 * TILE], g_m1l[2][16 * TILE];
__device__ __half g_b1h[2][16 * TILE], g_b1l[2][16 * TILE];
__device__ __half g_m2h[2][16 * TILE], g_m2l[2][16 * TILE];
__device__ __half g_b2h[2][16 * TILE], g_b2l[2][16 * TILE];
__device__ __half g_d1h[16 * TILE], g_d1l[16 * TILE];
__device__ __half g_d2h[16 * TILE], g_d2l[16 * TILE];
// ---- fp32 state/scratch (batch-major [b][n]) ----
__device__ float g_st[12 * BH];              // [parity][6][BH]
__device__ float g_m3[2 * B * O];
__device__ float g_d1[BH], g_d2[BH];
__device__ float g_part[18 * BH];            // dense partials (18 splits)
__device__ float g_pma[18 * BH];             // tau partials [z*9+s][BH]
__device__ unsigned g_arrive, g_phasec;

// ---------------------------------------------------------------------------
__device__ __forceinline__ float sigmf(float x) { return 1.0f / (1.0f + expf(-x)); }
#define SW128(o) ((o) ^ (((o) >> 3) & 0x70))

__device__ __forceinline__ void cpa16(void* dst_smem, const void* src) {
    unsigned d = (unsigned)__cvta_generic_to_shared(dst_smem);
    asm volatile("cp.async.cg.shared.global [%0], [%1], 16;\n" :: "r"(d), "l"(src));
}
__device__ __forceinline__ void cpa_commit() {
    asm volatile("cp.async.commit_group;\n" ::: "memory");
}
__device__ __forceinline__ void cpa_wait0() {
    asm volatile("cp.async.wait_group 0;\n" ::: "memory");
}
__device__ __forceinline__ unsigned smem_u32(const void* p) {
    return (unsigned)__cvta_generic_to_shared(p);
}
__device__ __forceinline__ void ldsm4(unsigned* r, unsigned addr) {
    asm volatile("ldmatrix.sync.aligned.m8n8.x4.shared.b16 {%0,%1,%2,%3}, [%4];"
        : "=r"(r[0]), "=r"(r[1]), "=r"(r[2]), "=r"(r[3]) : "r"(addr));
}
__device__ __forceinline__ void mma16816(float* d, const unsigned* a,
                                         unsigned b0, unsigned b1) {
    asm volatile(
        "mma.sync.aligned.m16n8k16.row.col.f32.f16.f16.f32 "
        "{%0,%1,%2,%3}, {%4,%5,%6,%7}, {%8,%9}, {%0,%1,%2,%3};"
        : "+f"(d[0]), "+f"(d[1]), "+f"(d[2]), "+f"(d[3])
        : "r"(a[0]), "r"(a[1]), "r"(a[2]), "r"(a[3]), "r"(b0), "r"(b1));
}

// sense barrier: fast spin first, light nanosleep backoff after
__device__ __forceinline__ void grid_bar(unsigned& gen) {
    __syncthreads();
    if (threadIdx.x == 0) {
        __threadfence();
        unsigned t = atomicAdd(&g_arrive, 1u);
        if (t == NBLK - 1) {
            *(volatile unsigned*)&g_arrive = 0u;
            __threadfence();
            atomicAdd(&g_phasec, 1u);
        } else {
            volatile unsigned* ph = &g_phasec;
            int spins = 0;
            while (*ph == gen) { if (++spins > 64) __nanosleep(40); }
            __threadfence();
        }
    }
    __syncthreads();
    gen++;
}

__device__ __forceinline__ unsigned packh(__half a, __half b) {
    __half2 t = __halves2half2(a, b);
    return *(unsigned*)&t;
}
// write fp16 images (hi, optional lo) for 4 consecutive n at (b, n)
__device__ __forceinline__ void wr_img(__half* hi, __half* lo, int n, int b, float4 v) {
    int ii = (n >> 6) * TILE + b * 64 + (n & 63);
    __half h0 = __float2half_rn(v.x), h1 = __float2half_rn(v.y);
    __half h2 = __float2half_rn(v.z), h3 = __float2half_rn(v.w);
    __stcg((uint2*)(hi + ii), make_uint2(packh(h0, h1), packh(h2, h3)));
    if (lo) {
        __half l0 = __float2half_rn(v.x - __half2float(h0));
        __half l1 = __float2half_rn(v.y - __half2float(h1));
        __half l2 = __float2half_rn(v.z - __half2float(h2));
        __half l3 = __float2half_rn(v.w - __half2float(h3));
        __stcg((uint2*)(lo + ii), make_uint2(packh(l0, l1), packh(l2, l3)));
    }
}

// ---------------------------------------------------------------------------
// A-operand (activation) tile resolver. stage: 0=dense1, 1=dense2, 2=tau1, 3=tau2
// ---------------------------------------------------------------------------
__device__ __forceinline__ const __half* resolve_A(int stage, int z, int c, int t, int p) {
    if (stage == 0) {
        if (c < 33) {
            int idx = (c < 11) ? c : (c < 22 ? c - 11 : c - 22);
            const __half* base = (c >= 11 && c < 22) ? g_xl : g_xh;
            return base + ((size_t)t * 11 + idx) * TILE;
        }
        return g_spk1i[p] + (size_t)((c - 33) & 15) * TILE;
    }
    if (stage == 1) {
        int sub = c >> 4, cc = c & 15;
        return g_spk1i[sub < 2 ? (p ^ 1) : p] + (size_t)cc * TILE;
    }
    int sub = c >> 4, cc = c & 15, l = stage - 2;
    const __half* base;
    if (sub < 3) {
        base = (sub == 1) ? (l ? g_d2l : g_d1l) : (l ? g_d2h : g_d1h);
    } else {
        int s2 = sub - 3;
        if (!z) base = (s2 == 1) ? (l ? g_m2l[p] : g_m1l[p]) : (l ? g_m2h[p] : g_m1h[p]);
        else    base = (s2 == 1) ? (l ? g_b2l[p] : g_b1l[p]) : (l ? g_b2h[p] : g_b1h[p]);
    }
    return base + (size_t)cc * TILE;
}

// ---------------------------------------------------------------------------
// GEMM job via mma.sync: chunks [tb,te) -> partial[b][mt*128..+128].
// dsm: 2 x 32KB buffers (A act tile 16KB + W tile 16KB each).
// Warp grid: 4 m-quadrants (batch, 32 rows) x 2 n-halves (neuron, 64 cols).
// ---------------------------------------------------------------------------
__device__ void mma_run(const __half* Wimg, int stage, int z, int t, int p, int mt,
                        int tb, int te, float* __restrict__ partial, char* dsm)
{
    const int tid = threadIdx.x;
    const int warp = tid >> 5, lane = tid & 31;
    const int wm = warp >> 1;    // batch quadrant
    const int wn = warp & 1;     // neuron half
    const int nb = te - tb;
    if (nb <= 0) return;

    float acc[16][4];
    #pragma unroll
    for (int i = 0; i < 16; i++)
        acc[i][0] = acc[i][1] = acc[i][2] = acc[i][3] = 0.f;

    auto load_tile = [&](int c, int buf) {
        const char* ap = (const char*)resolve_A(stage, z, c, t, p);
        const char* wp = (const char*)(Wimg + ((size_t)c * 8 + mt) * TILE);
        char* ad = dsm + buf * 32768;
        char* wd = ad + 16384;
        #pragma unroll
        for (int i = 0; i < 4; i++) {
            int off = (tid + i * 256) * 16;
            int sw = SW128(off);
            cpa16(ad + sw, ap + off);
            cpa16(wd + sw, wp + off);
        }
        cpa_commit();
    };

    load_tile(tb, 0);
    for (int i = 0; i < nb; i++) {
        cpa_wait0();
        __syncthreads();                 // buffer i ready; compute i-1 done
        if (i + 1 < nb) load_tile(tb + i + 1, (i + 1) & 1);   // overlaps compute
        const char* ad = dsm + (i & 1) * 32768;
        const char* wd = ad + 16384;
        const unsigned ab = smem_u32(ad), wb = smem_u32(wd);

        #pragma unroll
        for (int ks = 0; ks < 4; ks++) {
            unsigned a0[4], a1[4];
            {
                int row = wm * 32 + (lane & 7) + ((lane >> 3) & 1) * 8;
                int kb = ks * 32 + (lane >> 4) * 16;
                ldsm4(a0, ab + SW128(row * 128 + kb));
                ldsm4(a1, ab + SW128((row + 16) * 128 + kb));
            }
            unsigned bf[4][4];
            #pragma unroll
            for (int nf = 0; nf < 4; nf++) {
                int nr = wn * 64 + nf * 16 + (lane & 7) + ((lane >> 4) & 1) * 8;
                int kb = ks * 32 + ((lane >> 3) & 1) * 16;
                ldsm4(bf[nf], wb + SW128(nr * 128 + kb));
            }
            #pragma unroll
            for (int nf = 0; nf < 4; nf++) {
                mma16816(acc[nf * 2 + 0],     a0, bf[nf][0], bf[nf][1]);
                mma16816(acc[nf * 2 + 1],     a0, bf[nf][2], bf[nf][3]);
                mma16816(acc[8 + nf * 2 + 0], a1, bf[nf][0], bf[nf][1]);
                mma16816(acc[8 + nf * 2 + 1], a1, bf[nf][2], bf[nf][3]);
            }
        }
    }
    __syncthreads();

    // epilogue: acc -> partial[b][mt*128 + n]
    const int ncol0 = mt * 128 + wn * 64 + (lane & 3) * 2;
    #pragma unroll
    for (int mf = 0; mf < 2; mf++) {
        const int row0 = wm * 32 + mf * 16 + (lane >> 2);
        #pragma unroll
        for (int n8 = 0; n8 < 8; n8++) {
            float* p0 = partial + (size_t)row0 * H + ncol0 + n8 * 8;
            float* p1 = partial + (size_t)(row0 + 8) * H + ncol0 + n8 * 8;
            __stcg((float2*)p0, make_float2(acc[mf * 8 + n8][0], acc[mf * 8 + n8][1]));
            __stcg((float2*)p1, make_float2(acc[mf * 8 + n8][2], acc[mf * 8 + n8][3]));
        }
    }
}

// ---------------------------------------------------------------------------
// persistent kernel (144 blocks)
// ---------------------------------------------------------------------------
__global__ void __launch_bounds__(256) snn_persist_k(
    const float* __restrict__ b1x, const float* __restrict__ b1r,
    const float* __restrict__ b1m, const float* __restrict__ b1a,
    const float* __restrict__ b2x, const float* __restrict__ b2r,
    const float* __restrict__ b2m, const float* __restrict__ b2a,
    const float* __restrict__ w3x, const float* __restrict__ b3x,
    const float* __restrict__ w3m, const float* __restrict__ b3m,
    float* __restrict__ out)
{
    extern __shared__ __align__(1024) char dsm[];   // 64 KB dynamic

    const int bid = blockIdx.x, tid = threadIdx.x;
    unsigned gen = 0;

    #define STQ(pp, ss) (g_st + ((size_t)(pp) * 6 + (ss)) * BH)

    for (int t = 0; t < T; t++) {
        const int p = t & 1, q = p ^ 1;

        // ---- P1: dense1 MMA (65 chunks; 8 mt x 18 splits) ----
        {
            const int mt = bid & 7, s = bid >> 3;   // s in 0..17
            mma_run(g_wd1, 0, 0, t, p, mt, (65 * s) / 18, (65 * (s + 1)) / 18,
                    g_part + (size_t)s * BH, dsm);
        }
        grid_bar(gen);

        // ---- P2: reduce D1 (18 slices) + D1 images ----
        {
            const int idx = bid * 256 + tid;
            if (idx < BH / 4) {
                const size_t off = (size_t)idx * 4;
                float4 s4 = make_float4(0.f, 0.f, 0.f, 0.f);
                #pragma unroll
                for (int k = 0; k < 18; k++) {
                    float4 pp = __ldcg((const float4*)(g_part + (size_t)k * BH + off));
                    s4.x += pp.x; s4.y += pp.y; s4.z += pp.z; s4.w += pp.w;
                }
                const int b = (int)(off >> 10), n = (int)(off & 1023);
                float4 bx = *(const float4*)(b1x + n), br = *(const float4*)(b1r + n);
                float4 r = make_float4(SCALE * (s4.x + bx.x + br.x), SCALE * (s4.y + bx.y + br.y),
                                       SCALE * (s4.z + bx.z + br.z), SCALE * (s4.w + bx.w + br.w));
                __stcg((float4*)(g_d1 + off), r);
                wr_img(g_d1h, g_d1l, n, b, r);
            }
        }
        grid_bar(gen);

        // ---- P3: tau1 MMA (96 chunks per z; 8mt x 9s x 2z) ----
        {
            const int mt = bid & 7, s = (bid >> 3) % 9, z = bid / 72;
            mma_run(z ? g_wt1a : g_wt1m, 2, z, t, p, mt,
                    (96 * s) / 9, (96 * (s + 1)) / 9,
                    g_pma + (size_t)(z * 9 + s) * BH, dsm);
        }
        grid_bar(gen);

        // ---- P4: tau1 reduce + adaptive update -> parity q (+ images[q]) ----
        {
            const int idx = bid * 256 + tid;
            if (idx < BH / 4) {
                const size_t off = (size_t)idx * 4;
                float4 sm = make_float4(0.f, 0.f, 0.f, 0.f), sa = sm;
                #pragma unroll
                for (int k = 0; k < 9; k++) {
                    float4 pm = __ldcg((const float4*)(g_pma + (size_t)k * BH + off));
                    float4 pa = __ldcg((const float4*)(g_pma + (size_t)(9 + k) * BH + off));
                    sm.x += pm.x; sm.y += pm.y; sm.z += pm.z; sm.w += pm.w;
                    sa.x += pa.x; sa.y += pa.y; sa.z += pa.z; sa.w += pa.w;
                }
                const int b = (int)(off >> 10), n = (int)(off & 1023);
                float4 bm4 = *(const float4*)(b1m + n), ba4 = *(const float4*)(b1a + n);
                float4 dn = __ldcg((const float4*)(g_d1 + off));
                float4 me = __ldcg((const float4*)(STQ(p, MEM1) + off));
                float4 bo = __ldcg((const float4*)(STQ(p, BB1) + off));
                float4 sp = __ldcg((const float4*)(STQ(p, SPK1) + off));
                float tm[4] = { sigmf(sm.x + bm4.x), sigmf(sm.y + bm4.y),
                                sigmf(sm.z + bm4.z), sigmf(sm.w + bm4.w) };
                float ta[4] = { sigmf(sa.x + ba4.x), sigmf(sa.y + ba4.y),
                                sigmf(sa.z + ba4.z), sigmf(sa.w + ba4.w) };
                float dv[4] = { dn.x, dn.y, dn.z, dn.w }, mv[4] = { me.x, me.y, me.z, me.w };
                float bv[4] = { bo.x, bo.y, bo.z, bo.w }, sv[4] = { sp.x, sp.y, sp.z, sp.w };
                float nm[4], ns[4], nb[4];
                #pragma unroll
                for (int j = 0; j < 4; j++) {
                    float bn = ta[j] * bv[j] + (1.0f - ta[j]) * sv[j];
                    float mn = mv[j] + (dv[j] - mv[j]) * tm[j];
                    float s = (mn - (0.1f + 1.8f * bn)) > 0.0f ? 1.0f : 0.0f;
                    nm[j] = (1.0f - s) * mn; ns[j] = s; nb[j] = bn;
                }
                float4 fm = make_float4(nm[0], nm[1], nm[2], nm[3]);
                float4 fs = make_float4(ns[0], ns[1], ns[2], ns[3]);
                float4 fb = make_float4(nb[0], nb[1], nb[2], nb[3]);
                __stcg((float4*)(STQ(q, MEM1) + off), fm);
                __stcg((float4*)(STQ(q, SPK1) + off), fs);
                __stcg((float4*)(STQ(q, BB1) + off), fb);
                wr_img(g_m1h[q], g_m1l[q], n, b, fm);
                wr_img(g_spk1i[q], 0, n, b, fs);
                wr_img(g_b1h[q], g_b1l[q], n, b, fb);
            }
        }
        grid_bar(gen);

        // ---- P5: dense2 MMA (64 chunks; 8 mt x 18 splits) ----
        {
            const int mt = bid & 7, s = bid >> 3;
            mma_run(g_wd2, 1, 0, t, p, mt, (64 * s) / 18, (64 * (s + 1)) / 18,
                    g_part + (size_t)s * BH, dsm);
        }
        grid_bar(gen);

        // ---- P6: reduce D2 + images ----
        {
            const int idx = bid * 256 + tid;
            if (idx < BH / 4) {
                const size_t off = (size_t)idx * 4;
                float4 s4 = make_float4(0.f, 0.f, 0.f, 0.f);
                #pragma unroll
                for (int k = 0; k < 18; k++) {
                    float4 pp = __ldcg((const float4*)(g_part + (size_t)k * BH + off));
                    s4.x += pp.x; s4.y += pp.y; s4.z += pp.z; s4.w += pp.w;
                }
                const int b = (int)(off >> 10), n = (int)(off & 1023);
                float4 bx = *(const float4*)(b2x + n), br = *(const float4*)(b2r + n);
                float4 r = make_float4(SCALE * (s4.x + bx.x + br.x), SCALE * (s4.y + bx.y + br.y),
                                       SCALE * (s4.z + bx.z + br.z), SCALE * (s4.w + bx.w + br.w));
                __stcg((float4*)(g_d2 + off), r);
                wr_img(g_d2h, g_d2l, n, b, r);
            }
        }
        grid_bar(gen);

        // ---- P7: tau2 MMA ----
        {
            const int mt = bid & 7, s = (bid >> 3) % 9, z = bid / 72;
            mma_run(z ? g_wt2a : g_wt2m, 3, z, t, p, mt,
                    (96 * s) / 9, (96 * (s + 1)) / 9,
                    g_pma + (size_t)(z * 9 + s) * BH, dsm);
        }
        grid_bar(gen);

        // ---- P8: tau2 reduce + update -> parity q, FUSED head (block = batch b) ----
        if (bid < B) {
            const int b = bid;
            const size_t off = ((size_t)bid * 256 + tid) * 4;  // b = bid, n = tid*4
            float4 sm = make_float4(0.f, 0.f, 0.f, 0.f), sa = sm;
            #pragma unroll
            for (int k = 0; k < 9; k++) {
                float4 pm = __ldcg((const float4*)(g_pma + (size_t)k * BH + off));
                float4 pa = __ldcg((const float4*)(g_pma + (size_t)(9 + k) * BH + off));
                sm.x += pm.x; sm.y += pm.y; sm.z += pm.z; sm.w += pm.w;
                sa.x += pa.x; sa.y += pa.y; sa.z += pa.z; sa.w += pa.w;
            }
            const int n = (int)(off & 1023);
            float4 bm4 = *(const float4*)(b2m + n), ba4 = *(const float4*)(b2a + n);
            float4 dn = __ldcg((const float4*)(g_d2 + off));
            float4 me = __ldcg((const float4*)(STQ(p, MEM2) + off));
            float4 bo = __ldcg((const float4*)(STQ(p, BB2) + off));
            float4 sp = __ldcg((const float4*)(STQ(p, SPK2) + off));
            float tm[4] = { sigmf(sm.x + bm4.x), sigmf(sm.y + bm4.y),
                            sigmf(sm.z + bm4.z), sigmf(sm.w + bm4.w) };
            float ta[4] = { sigmf(sa.x + ba4.x), sigmf(sa.y + ba4.y),
                            sigmf(sa.z + ba4.z), sigmf(sa.w + ba4.w) };
            float dv[4] = { dn.x, dn.y, dn.z, dn.w }, mv[4] = { me.x, me.y, me.z, me.w };
            float bv[4] = { bo.x, bo.y, bo.z, bo.w }, sv[4] = { sp.x, sp.y, sp.z, sp.w };
            float nm[4], ns[4], nb[4];
            #pragma unroll
            for (int j = 0; j < 4; j++) {
                float bn = ta[j] * bv[j] + (1.0f - ta[j]) * sv[j];
                float mn = mv[j] + (dv[j] - mv[j]) * tm[j];
                float s = (mn - (0.1f + 1.8f * bn)) > 0.0f ? 1.0f : 0.0f;
                nm[j] = (1.0f - s) * mn; ns[j] = s; nb[j] = bn;
            }
            float4 fm = make_float4(nm[0], nm[1], nm[2], nm[3]);
            float4 fs = make_float4(ns[0], ns[1], ns[2], ns[3]);
            float4 fb = make_float4(nb[0], nb[1], nb[2], nb[3]);
            __stcg((float4*)(STQ(q, MEM2) + off), fm);
            __stcg((float4*)(STQ(q, SPK2) + off), fs);
            __stcg((float4*)(STQ(q, BB2) + off), fb);
            wr_img(g_m2h[q], g_m2l[q], n, b, fm);
            wr_img(g_b2h[q], g_b2l[q], n, b, fb);

            // -- fused head: this block owns the full spk2 row of batch b --
            float* srow = (float*)dsm;         // 1024
            float* red = srow + 1024;          // 160
            float* d3s = red + 160;            // 20
            float* m3s = d3s + 20;             // 20
            float* nms = m3s + 20;             // 20
            *(float4*)(srow + tid * 4) = fs;
            __syncthreads();
            if (tid < 160) {
                const int o = tid >> 3, seg = tid & 7;
                const float* wr = w3x + (size_t)o * H + seg * 128;
                const float* ar = srow + seg * 128;
                float a = 0.f;
                #pragma unroll 4
                for (int k = 0; k < 128; k++) a += ar[k] * wr[k];
                red[tid] = a;
            }
            __syncthreads();
            if (tid < 20) {
                float s = 0.f;
                #pragma unroll
                for (int j = 0; j < 8; j++) s += red[tid * 8 + j];
                d3s[tid] = SCALE * (s + b3x[tid]);
                m3s[tid] = __ldcg(g_m3 + (size_t)p * B * O + b * O + tid);
            }
            __syncthreads();
            if (tid < 20) {
                const float* w = w3m + tid * (2 * O);
                float acc = b3m[tid];
                #pragma unroll
                for (int k = 0; k < O; k++) acc += d3s[k] * w[k] + m3s[k] * w[O + k];
                float tmv = sigmf(acc);
                float v = (1.0f - tmv) * m3s[tid] + d3s[tid] * tmv;
                nms[tid] = v;
                __stcg(g_m3 + (size_t)q * B * O + b * O + tid, v);
            }
            __syncthreads();
            if (tid == 0) {
                float mx = nms[0];
                #pragma unroll
                for (int o = 1; o < O; o++) mx = fmaxf(mx, nms[o]);
                float s = 0.f;
                #pragma unroll
                for (int o = 0; o < O; o++) s += expf(nms[o] - mx);
                float lse = logf(s) + mx;
                #pragma unroll
                for (int o = 0; o < O; o++)
                    out[(size_t)t * B * O + b * O + o] = nms[o] - lse;
            }
            __syncthreads();
        }
        // no trailing barrier: next P1 touches only P4-barriered data + g_part,
        // which no P8 straggler reads; bar-after-next-P1 orders g_pma reuse.
    }
    #undef STQ
}

// ---------------------------------------------------------------------------
// pre/post kernels
// ---------------------------------------------------------------------------
// x -> fp16 hi/lo tiles [t][chunk][b][64]
__global__ void pack_x_k(const float* __restrict__ in) {
    const int c = blockIdx.x, t = blockIdx.y;
    const int r = threadIdx.x >> 1, hf = (threadIdx.x & 1) * 32;
    const int k0 = c * 64 + hf;
    const float* sp = in + (size_t)r * T * DIN + (size_t)t * DIN + k0;
    size_t doff = ((size_t)t * 11 + c) * TILE + r * 64 + hf;
    #pragma unroll 8
    for (int i = 0; i < 32; i++) {
        float v = (k0 + i < DIN) ? sp[i] : 0.0f;
        __half hi = __float2half_rn(v);
        g_xh[doff + i] = hi;
        g_xl[doff + i] = __float2half_rn(v - __half2float(hi));
    }
}

// all 12 weight-pack jobs in one launch: grid (16, 8, 12)
__global__ void pack_w_all_k(
    const float* __restrict__ w1x, const float* __restrict__ w1r,
    const float* __restrict__ w2x, const float* __restrict__ w2r,
    const float* __restrict__ w1m, const float* __restrict__ w1a,
    const float* __restrict__ w2m, const float* __restrict__ w2a)
{
    const int c = blockIdx.x, mt = blockIdx.y, job = blockIdx.z;
    const float* src; int Ksrc, kb, climit;
    __half *dh1, *dh2, *dl;
    switch (job) {
        case 0:  src = w1x; Ksrc = DIN;   kb = 0;    climit = 11;
                 dh1 = g_wd1;                 dh2 = g_wd1 + (size_t)11 * T8; dl = g_wd1 + (size_t)22 * T8; break;
        case 1:  src = w1r; Ksrc = H;     kb = 0;    climit = 16;
                 dh1 = g_wd1 + (size_t)33 * T8; dh2 = 0; dl = g_wd1 + (size_t)49 * T8; break;
        case 2:  src = w2x; Ksrc = H;     kb = 0;    climit = 16;
                 dh1 = g_wd2;                 dh2 = 0; dl = g_wd2 + (size_t)16 * T8; break;
        case 3:  src = w2r; Ksrc = H;     kb = 0;    climit = 16;
                 dh1 = g_wd2 + (size_t)32 * T8; dh2 = 0; dl = g_wd2 + (size_t)48 * T8; break;
        case 4:  src = w1m; Ksrc = 2 * H; kb = 0;    climit = 16;
                 dh1 = g_wt1m;                dh2 = g_wt1m + (size_t)16 * T8; dl = g_wt1m + (size_t)32 * T8; break;
        case 5:  src = w1m; Ksrc = 2 * H; kb = 1024; climit = 16;
                 dh1 = g_wt1m + (size_t)48 * T8; dh2 = g_wt1m + (size_t)64 * T8; dl = g_wt1m + (size_t)80 * T8; break;
        case 6:  src = w1a; Ksrc = 2 * H; kb = 0;    climit = 16;
                 dh1 = g_wt1a;                dh2 = g_wt1a + (size_t)16 * T8; dl = g_wt1a + (size_t)32 * T8; break;
        case 7:  src = w1a; Ksrc = 2 * H; kb = 1024; climit = 16;
                 dh1 = g_wt1a + (size_t)48 * T8; dh2 = g_wt1a + (size_t)64 * T8; dl = g_wt1a + (size_t)80 * T8; break;
        case 8:  src = w2m; Ksrc = 2 * H; kb = 0;    climit = 16;
                 dh1 = g_wt2m;                dh2 = g_wt2m + (size_t)16 * T8; dl = g_wt2m + (size_t)32 * T8; break;
        case 9:  src = w2m; Ksrc = 2 * H; kb = 1024; climit = 16;
                 dh1 = g_wt2m + (size_t)48 * T8; dh2 = g_wt2m + (size_t)64 * T8; dl = g_wt2m + (size_t)80 * T8; break;
        case 10: src = w2a; Ksrc = 2 * H; kb = 0;    climit = 16;
                 dh1 = g_wt2a;                dh2 = g_wt2a + (size_t)16 * T8; dl = g_wt2a + (size_t)32 * T8; break;
        default: src = w2a; Ksrc = 2 * H; kb = 1024; climit = 16;
                 dh1 = g_wt2a + (size_t)48 * T8; dh2 = g_wt2a + (size_t)64 * T8; dl = g_wt2a + (size_t)80 * T8; break;
    }
    if (c >= climit) return;
    const int r = threadIdx.x >> 1, hf = (threadIdx.x & 1) * 32;
    const int k0 = kb + c * 64 + hf;
    const float* sp = src + (size_t)(mt * 128 + r) * Ksrc + k0;
    size_t doff = ((size_t)c * 8 + mt) * TILE + r * 64 + hf;
    #pragma unroll 8
    for (int i = 0; i < 32; i++) {
        float v = (k0 + i < Ksrc) ? sp[i] : 0.0f;
        __half hi = __float2half_rn(v);
        dh1[doff + i] = hi;
        if (dh2) dh2[doff + i] = hi;
        if (dl) dl[doff + i] = __float2half_rn(v - __half2float(hi));
    }
}

// initial states (batch-major copies + images, parity 0) + barrier init
__global__ void init_state_k(const float* h0, const float* h1, const float* h2,
                             const float* h3, const float* h4, const float* h5,
                             const float* h6) {
    if (blockIdx.x == 0 && threadIdx.x == 0) { g_arrive = 0u; g_phasec = 0u; }
    const int idx = blockIdx.x * 256 + threadIdx.x;
    const size_t off = (size_t)idx * 4;
    const int b = (int)(off >> 10), n = (int)(off & 1023);
    const float* hs[6] = { h0, h1, h2, h3, h4, h5 };
    for (int s = 0; s < 6; s++) {
        float4 v = *(const float4*)(hs[s] + off);
        *(float4*)(g_st + (size_t)s * BH + off) = v;
        if (s == MEM1) wr_img(g_m1h[0], g_m1l[0], n, b, v);
        else if (s == SPK1) wr_img(g_spk1i[0], 0, n, b, v);
        else if (s == BB1) wr_img(g_b1h[0], g_b1l[0], n, b, v);
        else if (s == MEM2) wr_img(g_m2h[0], g_m2l[0], n, b, v);
        else if (s == BB2) wr_img(g_b2h[0], g_b2l[0], n, b, v);
    }
    if (idx < B * O / 4)
        *(float4*)(g_m3 + off) = *(const float4*)(h6 + off);
}

// final: states parity 0 + m3 -> out tail
__global__ void copy_out_k(float* __restrict__ tail) {
    const size_t total = 6 * BH + B * O;
    const size_t off = ((size_t)blockIdx.x * 256 + threadIdx.x) * 4;
    if (off >= total) return;
    float4 v;
    if (off < 6 * BH) v = *(const float4*)(g_st + off);
    else              v = *(const float4*)(g_m3 + (off - 6 * BH));
    *(float4*)(tail + off) = v;
}

// ---------------------------------------------------------------------------
extern "C" void kernel_launch(void* const* d_in, const int* in_sizes, int n_in,
                              void* d_out, int out_size)
{
    (void)in_sizes; (void)n_in; (void)out_size;
    const float* inputs = (const float*)d_in[0];
    const float* h[7];
    for (int i = 0; i < 7; i++) h[i] = (const float*)d_in[1 + i];
    const float* w1x = (const float*)d_in[8];  const float* b1x = (const float*)d_in[9];
    const float* w1r = (const float*)d_in[10]; const float* b1r = (const float*)d_in[11];
    const float* w1m = (const float*)d_in[12]; const float* b1m = (const float*)d_in[13];
    const float* w1a = (const float*)d_in[14]; const float* b1a = (const float*)d_in[15];
    const float* w2x = (const float*)d_in[16]; const float* b2x = (const float*)d_in[17];
    const float* w2r = (const float*)d_in[18]; const float* b2r = (const float*)d_in[19];
    const float* w2m = (const float*)d_in[20]; const float* b2m = (const float*)d_in[21];
    const float* w2a = (const float*)d_in[22]; const float* b2a = (const float*)d_in[23];
    const float* w3x = (const float*)d_in[24]; const float* b3x = (const float*)d_in[25];
    const float* w3m = (const float*)d_in[26]; const float* b3m = (const float*)d_in[27];
    float* out = (float*)d_out;

    cudaFuncSetAttribute(snn_persist_k, cudaFuncAttributeMaxDynamicSharedMemorySize, 65536);

    // persist is my 4th launch (global #6 with 2 harness pre-launches)
    pack_x_k<<<dim3(11, T), 256>>>(inputs);
    pack_w_all_k<<<dim3(16, 8, 12), 256>>>(w1x, w1r, w2x, w2r, w1m, w1a, w2m, w2a);
    init_state_k<<<128, 256>>>(h[0], h[1], h[2], h[3], h[4], h[5], h[6]);

    snn_persist_k<<<NBLK, 256, 65536>>>(b1x, b1r, b1m, b1a, b2x, b2r, b2m, b2a,
                                        w3x, b3x, w3m, b3m, out);

    copy_out_k<<<(6 * BH + B * O + 1023) / 1024, 256>>>(out + (size_t)T * B * O);
}